// round 11
// baseline (speedup 1.0000x reference)
#include <cuda_runtime.h>
#include <cuda_bf16.h>
#include <math.h>

#define N_NODES 10000
#define N_EDGES 160000
#define N_GRAPHS 64
#define HID 128
#define LAT 64
#define NLAY 3
#define ET 128         // edges per block in the edge kernel
#define NB 8           // nodes per block in node_kernel

// ---------------- device scratch (no allocations allowed) ----------------
__device__ float d_h[N_NODES * HID];
__device__ float d_aggr[N_NODES * HID];   // zero at load; node_kernel re-zeros after reading
// B-fragment packed weights: per (layer, kstep, ntile, lane) a uint4 {hi01, hi89, lo01, lo89}
__device__ uint4 d_W1f[NLAY * 16 * 32 * 32];   // GEMM1: K=256 (16 steps), N=256 (32 ntiles)
__device__ uint4 d_W2f[NLAY * 16 * 16 * 32];   // GEMM2: K=256 (16 steps), N=128 (16 ntiles)
__device__ float d_W1tail[NLAY * 256];         // k=256 column (edge_attr weight)
__device__ float d_Wgt[NLAY * 256 * HID];      // gate_W transposed
__device__ float d_sums[N_GRAPHS * HID];
__device__ float d_counts[N_GRAPHS];

__device__ __forceinline__ float sigmoidf_(float v) {
    return 1.f / (1.f + __expf(-v));
}
__device__ __forceinline__ unsigned pk2(float lo, float hi) {
    unsigned r;
    asm("cvt.rn.bf16x2.f32 %0, %1, %2;" : "=r"(r) : "f"(hi), "f"(lo));
    return r;
}
__device__ __forceinline__ void mma_bf16(float c[4],
                                         unsigned a0, unsigned a1, unsigned a2, unsigned a3,
                                         unsigned b0, unsigned b1) {
    asm("mma.sync.aligned.m16n8k16.row.col.f32.bf16.bf16.f32 "
        "{%0,%1,%2,%3}, {%4,%5,%6,%7}, {%8,%9}, {%0,%1,%2,%3};"
        : "+f"(c[0]), "+f"(c[1]), "+f"(c[2]), "+f"(c[3])
        : "r"(a0), "r"(a1), "r"(a2), "r"(a3), "r"(b0), "r"(b1));
}
__device__ __forceinline__ void ldsm4(unsigned r[4], unsigned addr) {
    asm volatile("ldmatrix.sync.aligned.m8n8.x4.shared.b16 {%0,%1,%2,%3}, [%4];"
        : "=r"(r[0]), "=r"(r[1]), "=r"(r[2]), "=r"(r[3]) : "r"(addr));
}

__device__ __forceinline__ float block_sum128(float v, float* red, int j) {
    red[j] = v;
    __syncthreads();
    #pragma unroll
    for (int s = 64; s > 0; s >>= 1) {
        if (j < s) red[j] += red[j + s];
        __syncthreads();
    }
    float r = red[0];
    __syncthreads();
    return r;
}

// ---------------- weight fragment packing (run once per launch) ----------------
__global__ void pack_kernel(const float* __restrict__ W1,   // [3][256][257]
                            const float* __restrict__ W2,   // [3][128][256]
                            const float* __restrict__ Wg) { // [3][128][256]
    int idx = blockIdx.x * blockDim.x + threadIdx.x;
    int stride = gridDim.x * blockDim.x;
    const int n1 = NLAY * 16 * 32 * 32;
    for (int t = idx; t < n1; t += stride) {
        int l = t / (16 * 32 * 32);
        int r = t % (16 * 32 * 32);
        int s = r / (32 * 32);
        int r2 = r % (32 * 32);
        int tt = r2 / 32;
        int lane = r2 % 32;
        int n = tt * 8 + lane / 4;
        int k0 = s * 16 + (lane % 4) * 2;
        const float* row = W1 + (l * 256 + n) * 257;
        float f0 = row[k0], f1 = row[k0 + 1], f2 = row[k0 + 8], f3 = row[k0 + 9];
        unsigned h01 = pk2(f0, f1);
        unsigned h89 = pk2(f2, f3);
        float a0 = __uint_as_float(h01 << 16), a1 = __uint_as_float(h01 & 0xFFFF0000u);
        float a2 = __uint_as_float(h89 << 16), a3 = __uint_as_float(h89 & 0xFFFF0000u);
        uint4 o;
        o.x = h01; o.y = h89;
        o.z = pk2(f0 - a0, f1 - a1);
        o.w = pk2(f2 - a2, f3 - a3);
        d_W1f[t] = o;
    }
    const int n2 = NLAY * 16 * 16 * 32;
    for (int t = idx; t < n2; t += stride) {
        int l = t / (16 * 16 * 32);
        int r = t % (16 * 16 * 32);
        int s = r / (16 * 32);
        int r2 = r % (16 * 32);
        int tt = r2 / 32;
        int lane = r2 % 32;
        int n = tt * 8 + lane / 4;
        int k0 = s * 16 + (lane % 4) * 2;
        const float* row = W2 + (l * 128 + n) * 256;
        float f0 = row[k0], f1 = row[k0 + 1], f2 = row[k0 + 8], f3 = row[k0 + 9];
        unsigned h01 = pk2(f0, f1);
        unsigned h89 = pk2(f2, f3);
        float a0 = __uint_as_float(h01 << 16), a1 = __uint_as_float(h01 & 0xFFFF0000u);
        float a2 = __uint_as_float(h89 << 16), a3 = __uint_as_float(h89 & 0xFFFF0000u);
        uint4 o;
        o.x = h01; o.y = h89;
        o.z = pk2(f0 - a0, f1 - a1);
        o.w = pk2(f2 - a2, f3 - a3);
        d_W2f[t] = o;
    }
    for (int t = idx; t < NLAY * 256; t += stride) {
        int l = t / 256;
        int j = t % 256;
        d_W1tail[t] = W1[(l * 256 + j) * 257 + 256];
    }
    const int n3 = NLAY * 128 * 256;
    for (int t = idx; t < n3; t += stride) {
        int l = t / (128 * 256);
        int r = t % (128 * 256);
        int i = r / 256;
        int k = r % 256;
        d_Wgt[l * 256 * 128 + k * 128 + i] = Wg[t];
    }
}

// ---------------- node embedding ----------------
__global__ void embed_kernel(const float* __restrict__ x,
                             const float* __restrict__ W,
                             const float* __restrict__ b,
                             const float* __restrict__ lng,
                             const float* __restrict__ lnb) {
    __shared__ float red[HID];
    int n = blockIdx.x;
    int j = threadIdx.x;
    float x0 = x[n * 3 + 0], x1 = x[n * 3 + 1], x2 = x[n * 3 + 2];
    float v = b[j] + x0 * W[j * 3 + 0] + x1 * W[j * 3 + 1] + x2 * W[j * 3 + 2];
    float m = block_sum128(v, red, j) * (1.f / HID);
    float d = v - m;
    float var = block_sum128(d * d, red, j) * (1.f / HID);
    float y = d * rsqrtf(var + 1e-5f) * lng[j] + lnb[j];
    d_h[n * HID + j] = y * sigmoidf_(y);
}

__global__ void zero_pool_kernel() {
    int idx = blockIdx.x * blockDim.x + threadIdx.x;
    if (idx < N_GRAPHS * HID) d_sums[idx] = 0.f;
    if (idx < N_GRAPHS) d_counts[idx] = 0.f;
}

// ---------------- edge MLP via tensor cores (split-bf16, ET=128, 16 warps) ----
// Warps: wm = w>>3 (M-half, 64 edges each), wn = w&7 (N-group).
// GEMM1: each warp 4 mtiles x 4 ntiles; GEMM2: 4 mtiles x 2 ntiles.
// The two M-half warps sharing an N-group reuse the same weight fragments via L1.
__global__ void __launch_bounds__(512, 1) edge_kernel(
    const float* __restrict__ edge_attr,
    const int* __restrict__ edge_index,
    const float* __restrict__ b1_all,   // [3][256]
    const float* __restrict__ b2_all,   // [3][128]
    int l) {
    extern __shared__ __align__(16) unsigned sm[];
    unsigned* Zh = sm;                      // 128*132 words
    unsigned* Zl = sm + 128 * 132;
    int* dst_s = (int*)(sm + 2 * 128 * 132);
    int* src_s = dst_s + 128;
    float* ea_s = (float*)(src_s + 128);

    const int tid = threadIdx.x;
    const int lane = tid & 31, w = tid >> 5;
    const int wm = w >> 3, wn = w & 7;
    const int e0 = blockIdx.x * ET;

    if (tid < 128) { dst_s[tid] = edge_index[N_EDGES + e0 + tid]; ea_s[tid] = edge_attr[e0 + tid]; }
    else if (tid < 256) src_s[tid - 128] = edge_index[e0 + tid - 128];
    __syncthreads();

    // gather + fp32 -> bf16 hi/lo conversion (512 threads, 128 edges x 4 quarters)
    {
        int e = tid >> 2, q = tid & 3;
        int node = (q < 2) ? dst_s[e] : src_s[e];
        const float4* hp = (const float4*)(d_h + node * HID + (q & 1) * 64);
        unsigned* oh = Zh + e * 132 + q * 32;
        unsigned* ol = Zl + e * 132 + q * 32;
        #pragma unroll
        for (int i = 0; i < 16; ++i) {
            float4 v = hp[i];
            unsigned h0 = pk2(v.x, v.y), h1 = pk2(v.z, v.w);
            float a0 = __uint_as_float(h0 << 16), a1 = __uint_as_float(h0 & 0xFFFF0000u);
            float a2 = __uint_as_float(h1 << 16), a3 = __uint_as_float(h1 & 0xFFFF0000u);
            oh[i * 2] = h0; oh[i * 2 + 1] = h1;
            ol[i * 2] = pk2(v.x - a0, v.y - a1);
            ol[i * 2 + 1] = pk2(v.z - a2, v.w - a3);
        }
    }
    __syncthreads();

    const int r = lane >> 2, qk = lane & 3;
    const unsigned zh_base = (unsigned)__cvta_generic_to_shared(Zh);
    const unsigned zl_base = (unsigned)__cvta_generic_to_shared(Zl);
    // per-lane LDSM offset within an mtile; wm adds the 64-edge half offset
    const unsigned aoff = ((wm * 64 + (lane & 15)) * 132 + ((lane >> 4) << 2)) * 4;

    // ---- GEMM1 ----
    float c[4][4][4];
    #pragma unroll
    for (int m = 0; m < 4; ++m)
        #pragma unroll
        for (int t = 0; t < 4; ++t)
            #pragma unroll
            for (int k = 0; k < 4; ++k) c[m][t][k] = 0.f;

    for (int s = 0; s < 16; ++s) {
        unsigned Ah[4][4], Al[4][4];
        #pragma unroll
        for (int m = 0; m < 4; ++m) {
            unsigned toff = aoff + (m * 16 * 132 + s * 8) * 4;
            ldsm4(Ah[m], zh_base + toff);
            ldsm4(Al[m], zl_base + toff);
        }
        #pragma unroll
        for (int t = 0; t < 4; ++t) {
            uint4 wv = d_W1f[((l * 16 + s) * 32 + (wn * 4 + t)) * 32 + lane];
            #pragma unroll
            for (int m = 0; m < 4; ++m)
                mma_bf16(c[m][t], Ah[m][0], Ah[m][1], Ah[m][2], Ah[m][3], wv.x, wv.y);
            #pragma unroll
            for (int m = 0; m < 4; ++m)
                mma_bf16(c[m][t], Ah[m][0], Ah[m][1], Ah[m][2], Ah[m][3], wv.z, wv.w);
            #pragma unroll
            for (int m = 0; m < 4; ++m)
                mma_bf16(c[m][t], Al[m][0], Al[m][1], Al[m][2], Al[m][3], wv.x, wv.y);
        }
    }
    __syncthreads();   // all Z reads complete before overwrite

    // epilogue1: bias + edge_attr tail + silu -> bf16 hi/lo back into Zh/Zl
    #pragma unroll
    for (int m = 0; m < 4; ++m) {
        #pragma unroll
        for (int t = 0; t < 4; ++t) {
            int n0 = (wn * 4 + t) * 8 + qk * 2;
            int elo = wm * 64 + m * 16 + r, ehi = elo + 8;
            float bn0 = b1_all[l * 256 + n0], bn1 = b1_all[l * 256 + n0 + 1];
            float wt0 = d_W1tail[l * 256 + n0], wt1 = d_W1tail[l * 256 + n0 + 1];
            float el = ea_s[elo], eh = ea_s[ehi];
            float v00 = c[m][t][0] + bn0 + el * wt0;
            float v01 = c[m][t][1] + bn1 + el * wt1;
            float v10 = c[m][t][2] + bn0 + eh * wt0;
            float v11 = c[m][t][3] + bn1 + eh * wt1;
            v00 *= sigmoidf_(v00); v01 *= sigmoidf_(v01);
            v10 *= sigmoidf_(v10); v11 *= sigmoidf_(v11);
            int wlo = elo * 132 + (wn * 4 + t) * 4 + qk;
            int whi = ehi * 132 + (wn * 4 + t) * 4 + qk;
            unsigned h0 = pk2(v00, v01);
            unsigned h1 = pk2(v10, v11);
            float a0 = __uint_as_float(h0 << 16), a1 = __uint_as_float(h0 & 0xFFFF0000u);
            float a2 = __uint_as_float(h1 << 16), a3 = __uint_as_float(h1 & 0xFFFF0000u);
            Zh[wlo] = h0; Zl[wlo] = pk2(v00 - a0, v01 - a1);
            Zh[whi] = h1; Zl[whi] = pk2(v10 - a2, v11 - a3);
        }
    }
    __syncthreads();

    // ---- GEMM2 ----
    float c2[4][2][4];
    #pragma unroll
    for (int m = 0; m < 4; ++m)
        #pragma unroll
        for (int t = 0; t < 2; ++t)
            #pragma unroll
            for (int k = 0; k < 4; ++k) c2[m][t][k] = 0.f;

    for (int s = 0; s < 16; ++s) {
        unsigned Ah[4][4], Al[4][4];
        #pragma unroll
        for (int m = 0; m < 4; ++m) {
            unsigned toff = aoff + (m * 16 * 132 + s * 8) * 4;
            ldsm4(Ah[m], zh_base + toff);
            ldsm4(Al[m], zl_base + toff);
        }
        #pragma unroll
        for (int t = 0; t < 2; ++t) {
            uint4 wv = d_W2f[((l * 16 + s) * 16 + (wn * 2 + t)) * 32 + lane];
            #pragma unroll
            for (int m = 0; m < 4; ++m)
                mma_bf16(c2[m][t], Ah[m][0], Ah[m][1], Ah[m][2], Ah[m][3], wv.x, wv.y);
            #pragma unroll
            for (int m = 0; m < 4; ++m)
                mma_bf16(c2[m][t], Ah[m][0], Ah[m][1], Ah[m][2], Ah[m][3], wv.z, wv.w);
            #pragma unroll
            for (int m = 0; m < 4; ++m)
                mma_bf16(c2[m][t], Al[m][0], Al[m][1], Al[m][2], Al[m][3], wv.x, wv.y);
        }
    }

    // epilogue2: bias + scatter-add
    #pragma unroll
    for (int m = 0; m < 4; ++m) {
        #pragma unroll
        for (int t = 0; t < 2; ++t) {
            int i0 = (wn * 2 + t) * 8 + qk * 2;
            int elo = wm * 64 + m * 16 + r, ehi = elo + 8;
            float bi0 = b2_all[l * 128 + i0], bi1 = b2_all[l * 128 + i0 + 1];
            int dlo = dst_s[elo], dhi = dst_s[ehi];
            atomicAdd(&d_aggr[dlo * HID + i0],     c2[m][t][0] + bi0);
            atomicAdd(&d_aggr[dlo * HID + i0 + 1], c2[m][t][1] + bi1);
            atomicAdd(&d_aggr[dhi * HID + i0],     c2[m][t][2] + bi0);
            atomicAdd(&d_aggr[dhi * HID + i0 + 1], c2[m][t][3] + bi1);
        }
    }
}

// ---------------- gated node update + residual + LN (NB nodes/block) --------
// Also re-zeroes d_aggr for the next layer/replay.
__global__ void __launch_bounds__(HID) node_kernel(
    const float* __restrict__ gb_all,
    const float* __restrict__ lng_all,
    const float* __restrict__ lnb_all,
    int l) {
    __shared__ float hn[NB][HID], an[NB][HID], red[NB][HID];
    int n0 = blockIdx.x * NB;
    int j = threadIdx.x;
    #pragma unroll
    for (int n = 0; n < NB; ++n) {
        hn[n][j] = d_h[(n0 + n) * HID + j];
        an[n][j] = d_aggr[(n0 + n) * HID + j];
        d_aggr[(n0 + n) * HID + j] = 0.f;
    }
    __syncthreads();

    const float* Wg = d_Wgt + l * 256 * HID;
    float g[NB];
    float gb0 = gb_all[l * HID + j];
    #pragma unroll
    for (int n = 0; n < NB; ++n) g[n] = gb0;
    for (int k = 0; k < HID; ++k) {
        float wv = Wg[k * HID + j];
        #pragma unroll
        for (int n = 0; n < NB; ++n) g[n] = fmaf(hn[n][k], wv, g[n]);
    }
    for (int k = 0; k < HID; ++k) {
        float wv = Wg[(HID + k) * HID + j];
        #pragma unroll
        for (int n = 0; n < NB; ++n) g[n] = fmaf(an[n][k], wv, g[n]);
    }

    float t[NB];
    #pragma unroll
    for (int n = 0; n < NB; ++n) {
        float gs = sigmoidf_(g[n]);
        float hnew = gs * an[n][j] + (1.f - gs) * hn[n][j];
        t[n] = hn[n][j] + hnew;
        red[n][j] = t[n];
    }
    __syncthreads();
    #pragma unroll
    for (int s = 64; s > 0; s >>= 1) {
        if (j < s)
            #pragma unroll
            for (int n = 0; n < NB; ++n) red[n][j] += red[n][j + s];
        __syncthreads();
    }
    float mean[NB];
    #pragma unroll
    for (int n = 0; n < NB; ++n) mean[n] = red[n][0] * (1.f / HID);
    __syncthreads();
    float dd[NB];
    #pragma unroll
    for (int n = 0; n < NB; ++n) { dd[n] = t[n] - mean[n]; red[n][j] = dd[n] * dd[n]; }
    __syncthreads();
    #pragma unroll
    for (int s = 64; s > 0; s >>= 1) {
        if (j < s)
            #pragma unroll
            for (int n = 0; n < NB; ++n) red[n][j] += red[n][j + s];
        __syncthreads();
    }
    float lg = lng_all[l * HID + j], lb = lnb_all[l * HID + j];
    #pragma unroll
    for (int n = 0; n < NB; ++n) {
        float var = red[n][0] * (1.f / HID);
        d_h[(n0 + n) * HID + j] = dd[n] * rsqrtf(var + 1e-5f) * lg + lb;
    }
}

// ---------------- pooling ----------------
__global__ void pool_kernel(const int* __restrict__ batch) {
    int n = blockIdx.x;
    int j = threadIdx.x;
    int g = batch[n];
    atomicAdd(&d_sums[g * HID + j], d_h[n * HID + j]);
    if (j == 0) atomicAdd(&d_counts[g], 1.f);
}

// ---------------- x_global + projector ----------------
__global__ void final_kernel(const float* __restrict__ W1, const float* __restrict__ b1,
                             const float* __restrict__ g1, const float* __restrict__ bb1,
                             const float* __restrict__ W2, const float* __restrict__ b2,
                             const float* __restrict__ g2, const float* __restrict__ bb2,
                             float* __restrict__ out) {
    __shared__ float xg[HID], p[HID], red[HID];
    int gr = blockIdx.x;
    int j = threadIdx.x;

    float c = d_counts[gr];
    float scale = 1.f / fmaxf(c, 1.f) + 1.f / (c + 1e-6f);
    float v = d_sums[gr * HID + j] * scale;
    xg[j] = v;
    out[N_GRAPHS * LAT + gr * HID + j] = v;
    __syncthreads();

    float a = b1[j];
    #pragma unroll 4
    for (int k = 0; k < HID; ++k) a = fmaf(xg[k], W1[j * HID + k], a);
    float m = block_sum128(a, red, j) * (1.f / HID);
    float d = a - m;
    float var = block_sum128(d * d, red, j) * (1.f / HID);
    a = d * rsqrtf(var + 1e-5f) * g1[j] + bb1[j];
    a = a * sigmoidf_(a);
    p[j] = a;
    __syncthreads();

    float z = 0.f;
    if (j < LAT) {
        z = b2[j];
        #pragma unroll 4
        for (int k = 0; k < HID; ++k) z = fmaf(p[k], W2[j * HID + k], z);
    }
    float m2 = block_sum128((j < LAT) ? z : 0.f, red, j) * (1.f / LAT);
    float d2 = z - m2;
    float var2 = block_sum128((j < LAT) ? d2 * d2 : 0.f, red, j) * (1.f / LAT);
    if (j < LAT)
        out[gr * LAT + j] = d2 * rsqrtf(var2 + 1e-5f) * g2[j] + bb2[j];
}

// ---------------- launch ----------------
extern "C" void kernel_launch(void* const* d_in, const int* in_sizes, int n_in,
                              void* d_out, int out_size) {
    const float* x     = (const float*)d_in[0];
    const float* ea    = (const float*)d_in[1];
    const int*   ei    = (const int*)  d_in[2];
    const int*   batch = (const int*)  d_in[3];
    const float* embW  = (const float*)d_in[4];
    const float* embb  = (const float*)d_in[5];
    const float* embg  = (const float*)d_in[6];
    const float* emblb = (const float*)d_in[7];
    const float* m1W   = (const float*)d_in[8];
    const float* m1b   = (const float*)d_in[9];
    const float* m2W   = (const float*)d_in[10];
    const float* m2b   = (const float*)d_in[11];
    const float* gW    = (const float*)d_in[12];
    const float* gb    = (const float*)d_in[13];
    const float* lng   = (const float*)d_in[14];
    const float* lnb   = (const float*)d_in[15];
    const float* p1W   = (const float*)d_in[16];
    const float* p1b   = (const float*)d_in[17];
    const float* pl1g  = (const float*)d_in[18];
    const float* pl1b  = (const float*)d_in[19];
    const float* p2W   = (const float*)d_in[20];
    const float* p2b   = (const float*)d_in[21];
    const float* pl2g  = (const float*)d_in[22];
    const float* pl2b  = (const float*)d_in[23];
    float* out = (float*)d_out;

    // smem: Zh+Zl (128*132*4*2 = 135168) + idx/ea (1536) = 136704 bytes
    const int smem_bytes = 2 * 128 * 132 * 4 + 3 * 128 * 4;
    cudaFuncSetAttribute(edge_kernel, cudaFuncAttributeMaxDynamicSharedMemorySize, smem_bytes);

    pack_kernel<<<384, 256>>>(m1W, m2W, gW);
    embed_kernel<<<N_NODES, HID>>>(x, embW, embb, embg, emblb);

    for (int l = 0; l < NLAY; ++l) {
        edge_kernel<<<N_EDGES / ET, 512, smem_bytes>>>(ea, ei, m1b, m2b, l);
        node_kernel<<<N_NODES / NB, HID>>>(gb, lng, lnb, l);
    }

    zero_pool_kernel<<<33, 256>>>();
    pool_kernel<<<N_NODES, HID>>>(batch);
    final_kernel<<<N_GRAPHS, HID>>>(p1W, p1b, pl1g, pl1b, p2W, p2b, pl2g, pl2b, out);
}

// round 12
// speedup vs baseline: 1.1083x; 1.1083x over previous
#include <cuda_runtime.h>
#include <cuda_bf16.h>
#include <math.h>

#define N_NODES 10000
#define N_EDGES 160000
#define N_GRAPHS 64
#define HID 128
#define LAT 64
#define NLAY 3
#define ET 64          // edges per block in the edge kernel
#define NB 8           // nodes per block in node_kernel

// ---------------- device scratch (no allocations allowed) ----------------
__device__ float d_h[N_NODES * HID];
__device__ float d_aggr[N_NODES * HID];   // zero at load; node_kernel re-zeros after reading
// B-fragment packed weights: per (layer, kstep, ntile, lane) a uint4 {hi01, hi89, lo01, lo89}
__device__ uint4 d_W1f[NLAY * 16 * 32 * 32];   // GEMM1: K=256 (16 steps), N=256 (32 ntiles)
__device__ uint4 d_W2f[NLAY * 16 * 16 * 32];   // GEMM2: K=256 (16 steps), N=128 (16 ntiles)
__device__ float d_W1tail[NLAY * 256];         // k=256 column (edge_attr weight)
__device__ float d_Wgt[NLAY * 256 * HID];      // gate_W transposed
__device__ float d_sums[N_GRAPHS * HID];
__device__ float d_counts[N_GRAPHS];

__device__ __forceinline__ float sigmoidf_(float v) {
    return 1.f / (1.f + __expf(-v));
}
__device__ __forceinline__ unsigned pk2(float lo, float hi) {
    unsigned r;
    asm("cvt.rn.bf16x2.f32 %0, %1, %2;" : "=r"(r) : "f"(hi), "f"(lo));
    return r;
}
__device__ __forceinline__ void mma_bf16(float c[4],
                                         unsigned a0, unsigned a1, unsigned a2, unsigned a3,
                                         unsigned b0, unsigned b1) {
    asm("mma.sync.aligned.m16n8k16.row.col.f32.bf16.bf16.f32 "
        "{%0,%1,%2,%3}, {%4,%5,%6,%7}, {%8,%9}, {%0,%1,%2,%3};"
        : "+f"(c[0]), "+f"(c[1]), "+f"(c[2]), "+f"(c[3])
        : "r"(a0), "r"(a1), "r"(a2), "r"(a3), "r"(b0), "r"(b1));
}
__device__ __forceinline__ void ldsm4(unsigned r[4], unsigned addr) {
    asm volatile("ldmatrix.sync.aligned.m8n8.x4.shared.b16 {%0,%1,%2,%3}, [%4];"
        : "=r"(r[0]), "=r"(r[1]), "=r"(r[2]), "=r"(r[3]) : "r"(addr));
}
__device__ __forceinline__ void cpasync16(unsigned saddr, const void* g) {
    asm volatile("cp.async.ca.shared.global [%0], [%1], 16;" :: "r"(saddr), "l"(g));
}
#define CP_COMMIT() asm volatile("cp.async.commit_group;")
#define CP_WAIT1()  asm volatile("cp.async.wait_group 1;")
#define CP_WAIT0()  asm volatile("cp.async.wait_group 0;")

__device__ __forceinline__ float block_sum128(float v, float* red, int j) {
    red[j] = v;
    __syncthreads();
    #pragma unroll
    for (int s = 64; s > 0; s >>= 1) {
        if (j < s) red[j] += red[j + s];
        __syncthreads();
    }
    float r = red[0];
    __syncthreads();
    return r;
}

// ---------------- weight fragment packing (run once per launch) ----------------
__global__ void pack_kernel(const float* __restrict__ W1,   // [3][256][257]
                            const float* __restrict__ W2,   // [3][128][256]
                            const float* __restrict__ Wg) { // [3][128][256]
    int idx = blockIdx.x * blockDim.x + threadIdx.x;
    int stride = gridDim.x * blockDim.x;
    const int n1 = NLAY * 16 * 32 * 32;
    for (int t = idx; t < n1; t += stride) {
        int l = t / (16 * 32 * 32);
        int r = t % (16 * 32 * 32);
        int s = r / (32 * 32);
        int r2 = r % (32 * 32);
        int tt = r2 / 32;
        int lane = r2 % 32;
        int n = tt * 8 + lane / 4;
        int k0 = s * 16 + (lane % 4) * 2;
        const float* row = W1 + (l * 256 + n) * 257;
        float f0 = row[k0], f1 = row[k0 + 1], f2 = row[k0 + 8], f3 = row[k0 + 9];
        unsigned h01 = pk2(f0, f1);
        unsigned h89 = pk2(f2, f3);
        float a0 = __uint_as_float(h01 << 16), a1 = __uint_as_float(h01 & 0xFFFF0000u);
        float a2 = __uint_as_float(h89 << 16), a3 = __uint_as_float(h89 & 0xFFFF0000u);
        uint4 o;
        o.x = h01; o.y = h89;
        o.z = pk2(f0 - a0, f1 - a1);
        o.w = pk2(f2 - a2, f3 - a3);
        d_W1f[t] = o;
    }
    const int n2 = NLAY * 16 * 16 * 32;
    for (int t = idx; t < n2; t += stride) {
        int l = t / (16 * 16 * 32);
        int r = t % (16 * 16 * 32);
        int s = r / (16 * 32);
        int r2 = r % (16 * 32);
        int tt = r2 / 32;
        int lane = r2 % 32;
        int n = tt * 8 + lane / 4;
        int k0 = s * 16 + (lane % 4) * 2;
        const float* row = W2 + (l * 128 + n) * 256;
        float f0 = row[k0], f1 = row[k0 + 1], f2 = row[k0 + 8], f3 = row[k0 + 9];
        unsigned h01 = pk2(f0, f1);
        unsigned h89 = pk2(f2, f3);
        float a0 = __uint_as_float(h01 << 16), a1 = __uint_as_float(h01 & 0xFFFF0000u);
        float a2 = __uint_as_float(h89 << 16), a3 = __uint_as_float(h89 & 0xFFFF0000u);
        uint4 o;
        o.x = h01; o.y = h89;
        o.z = pk2(f0 - a0, f1 - a1);
        o.w = pk2(f2 - a2, f3 - a3);
        d_W2f[t] = o;
    }
    for (int t = idx; t < NLAY * 256; t += stride) {
        int l = t / 256;
        int j = t % 256;
        d_W1tail[t] = W1[(l * 256 + j) * 257 + 256];
    }
    const int n3 = NLAY * 128 * 256;
    for (int t = idx; t < n3; t += stride) {
        int l = t / (128 * 256);
        int r = t % (128 * 256);
        int i = r / 256;
        int k = r % 256;
        d_Wgt[l * 256 * 128 + k * 128 + i] = Wg[t];
    }
}

// ---------------- node embedding ----------------
__global__ void embed_kernel(const float* __restrict__ x,
                             const float* __restrict__ W,
                             const float* __restrict__ b,
                             const float* __restrict__ lng,
                             const float* __restrict__ lnb) {
    __shared__ float red[HID];
    int n = blockIdx.x;
    int j = threadIdx.x;
    float x0 = x[n * 3 + 0], x1 = x[n * 3 + 1], x2 = x[n * 3 + 2];
    float v = b[j] + x0 * W[j * 3 + 0] + x1 * W[j * 3 + 1] + x2 * W[j * 3 + 2];
    float m = block_sum128(v, red, j) * (1.f / HID);
    float d = v - m;
    float var = block_sum128(d * d, red, j) * (1.f / HID);
    float y = d * rsqrtf(var + 1e-5f) * lng[j] + lnb[j];
    d_h[n * HID + j] = y * sigmoidf_(y);
}

__global__ void zero_pool_kernel() {
    int idx = blockIdx.x * blockDim.x + threadIdx.x;
    if (idx < N_GRAPHS * HID) d_sums[idx] = 0.f;
    if (idx < N_GRAPHS) d_counts[idx] = 0.f;
}

// ---------------- edge MLP via tensor cores (split-bf16, per-warp cp.async pipe)
// ET=64, 256 threads, 2 CTAs/SM (R7 config). Weight fragments are prefetched
// one s-step ahead into per-warp private SMEM slots via cp.async; waits are
// per-thread wait_group only — no block barriers added.
__global__ void __launch_bounds__(256, 2) edge_kernel(
    const float* __restrict__ edge_attr,
    const int* __restrict__ edge_index,
    const float* __restrict__ b1_all,   // [3][256]
    const float* __restrict__ b2_all,   // [3][128]
    int l) {
    extern __shared__ __align__(16) unsigned sm[];
    unsigned* Zh = sm;                      // 64*132 words
    unsigned* Zl = sm + 64 * 132;
    int* dst_s = (int*)(sm + 2 * 64 * 132);
    int* src_s = dst_s + 64;
    float* ea_s = (float*)(src_s + 64);
    // per-warp weight staging: 8 warps x 2 stages x 128 uint4 = 2048 uint4 (32KB)
    uint4* Wst = (uint4*)(sm + 2 * 64 * 132 + 192);

    const int tid = threadIdx.x;
    const int lane = tid & 31, w = tid >> 5;
    const int e0 = blockIdx.x * ET;

    uint4* wslot = Wst + w * 256;                         // this warp's 2-stage region
    const unsigned wslot_sm = (unsigned)__cvta_generic_to_shared(wslot);
    const uint4* W1base = d_W1f + (l * 16) * 32 * 32;
    const uint4* W2base = d_W2f + (l * 16) * 16 * 32;

    // prologue: prefetch GEMM1 s=0 into stage 0 (overlaps gather below)
    #pragma unroll
    for (int t = 0; t < 4; ++t)
        cpasync16(wslot_sm + (t * 32 + lane) * 16, W1base + (w * 4 + t) * 32 + lane);
    CP_COMMIT();

    if (tid < 64) { dst_s[tid] = edge_index[N_EDGES + e0 + tid]; ea_s[tid] = edge_attr[e0 + tid]; }
    else if (tid < 128) src_s[tid - 64] = edge_index[e0 + tid - 64];
    __syncthreads();

    // gather + fp32 -> bf16 hi/lo conversion
    {
        int e = tid >> 2, q = tid & 3;
        int node = (q < 2) ? dst_s[e] : src_s[e];
        const float4* hp = (const float4*)(d_h + node * HID + (q & 1) * 64);
        unsigned* oh = Zh + e * 132 + q * 32;
        unsigned* ol = Zl + e * 132 + q * 32;
        #pragma unroll
        for (int i = 0; i < 16; ++i) {
            float4 v = hp[i];
            unsigned h0 = pk2(v.x, v.y), h1 = pk2(v.z, v.w);
            float a0 = __uint_as_float(h0 << 16), a1 = __uint_as_float(h0 & 0xFFFF0000u);
            float a2 = __uint_as_float(h1 << 16), a3 = __uint_as_float(h1 & 0xFFFF0000u);
            oh[i * 2] = h0; oh[i * 2 + 1] = h1;
            ol[i * 2] = pk2(v.x - a0, v.y - a1);
            ol[i * 2 + 1] = pk2(v.z - a2, v.w - a3);
        }
    }
    __syncthreads();

    const int r = lane >> 2, qk = lane & 3;
    const unsigned zh_base = (unsigned)__cvta_generic_to_shared(Zh);
    const unsigned zl_base = (unsigned)__cvta_generic_to_shared(Zl);
    const unsigned aoff = ((lane & 15) * 132 + ((lane >> 4) << 2)) * 4;

    // ---- GEMM1 ----
    float c[4][4][4];
    #pragma unroll
    for (int m = 0; m < 4; ++m)
        #pragma unroll
        for (int t = 0; t < 4; ++t)
            #pragma unroll
            for (int k = 0; k < 4; ++k) c[m][t][k] = 0.f;

    for (int s = 0; s < 16; ++s) {
        if (s < 15) {   // prefetch next step into the other stage
            const uint4* src = W1base + (s + 1) * 1024 + (w * 4) * 32 + lane;
            unsigned dst = wslot_sm + (((s + 1) & 1) * 128 + lane) * 16;
            #pragma unroll
            for (int t = 0; t < 4; ++t)
                cpasync16(dst + t * 512, src + t * 32);
            CP_COMMIT();
            CP_WAIT1();   // stage s ready (per-thread, no barrier)
        } else {
            CP_WAIT0();
        }
        unsigned Ah[4][4], Al[4][4];
        #pragma unroll
        for (int m = 0; m < 4; ++m) {
            unsigned toff = aoff + (m * 16 * 132 + s * 8) * 4;
            ldsm4(Ah[m], zh_base + toff);
            ldsm4(Al[m], zl_base + toff);
        }
        const uint4* buf = wslot + (s & 1) * 128;
        #pragma unroll
        for (int t = 0; t < 4; ++t) {
            uint4 wv = buf[t * 32 + lane];
            #pragma unroll
            for (int m = 0; m < 4; ++m)
                mma_bf16(c[m][t], Ah[m][0], Ah[m][1], Ah[m][2], Ah[m][3], wv.x, wv.y);
            #pragma unroll
            for (int m = 0; m < 4; ++m)
                mma_bf16(c[m][t], Ah[m][0], Ah[m][1], Ah[m][2], Ah[m][3], wv.z, wv.w);
            #pragma unroll
            for (int m = 0; m < 4; ++m)
                mma_bf16(c[m][t], Al[m][0], Al[m][1], Al[m][2], Al[m][3], wv.x, wv.y);
        }
    }

    // prefetch GEMM2 s=0 into stage 0 (overlaps epilogue1 math)
    #pragma unroll
    for (int t = 0; t < 2; ++t)
        cpasync16(wslot_sm + (t * 32 + lane) * 16, W2base + (w * 2 + t) * 32 + lane);
    CP_COMMIT();
    __syncthreads();   // all Z reads complete before overwrite

    // epilogue1: bias + edge_attr tail + silu -> bf16 hi/lo back into Zh/Zl
    #pragma unroll
    for (int m = 0; m < 4; ++m) {
        #pragma unroll
        for (int t = 0; t < 4; ++t) {
            int n0 = (w * 4 + t) * 8 + qk * 2;
            int elo = m * 16 + r, ehi = elo + 8;
            float bn0 = b1_all[l * 256 + n0], bn1 = b1_all[l * 256 + n0 + 1];
            float wt0 = d_W1tail[l * 256 + n0], wt1 = d_W1tail[l * 256 + n0 + 1];
            float el = ea_s[elo], eh = ea_s[ehi];
            float v00 = c[m][t][0] + bn0 + el * wt0;
            float v01 = c[m][t][1] + bn1 + el * wt1;
            float v10 = c[m][t][2] + bn0 + eh * wt0;
            float v11 = c[m][t][3] + bn1 + eh * wt1;
            v00 *= sigmoidf_(v00); v01 *= sigmoidf_(v01);
            v10 *= sigmoidf_(v10); v11 *= sigmoidf_(v11);
            int wlo = elo * 132 + (w * 4 + t) * 4 + qk;
            int whi = ehi * 132 + (w * 4 + t) * 4 + qk;
            unsigned h0 = pk2(v00, v01);
            unsigned h1 = pk2(v10, v11);
            float a0 = __uint_as_float(h0 << 16), a1 = __uint_as_float(h0 & 0xFFFF0000u);
            float a2 = __uint_as_float(h1 << 16), a3 = __uint_as_float(h1 & 0xFFFF0000u);
            Zh[wlo] = h0; Zl[wlo] = pk2(v00 - a0, v01 - a1);
            Zh[whi] = h1; Zl[whi] = pk2(v10 - a2, v11 - a3);
        }
    }
    __syncthreads();

    // ---- GEMM2 ----
    float c2[4][2][4];
    #pragma unroll
    for (int m = 0; m < 4; ++m)
        #pragma unroll
        for (int t = 0; t < 2; ++t)
            #pragma unroll
            for (int k = 0; k < 4; ++k) c2[m][t][k] = 0.f;

    for (int s = 0; s < 16; ++s) {
        if (s < 15) {
            const uint4* src = W2base + (s + 1) * 512 + (w * 2) * 32 + lane;
            unsigned dst = wslot_sm + (((s + 1) & 1) * 128 + lane) * 16;
            #pragma unroll
            for (int t = 0; t < 2; ++t)
                cpasync16(dst + t * 512, src + t * 32);
            CP_COMMIT();
            CP_WAIT1();
        } else {
            CP_WAIT0();
        }
        unsigned Ah[4][4], Al[4][4];
        #pragma unroll
        for (int m = 0; m < 4; ++m) {
            unsigned toff = aoff + (m * 16 * 132 + s * 8) * 4;
            ldsm4(Ah[m], zh_base + toff);
            ldsm4(Al[m], zl_base + toff);
        }
        const uint4* buf = wslot + (s & 1) * 128;
        #pragma unroll
        for (int t = 0; t < 2; ++t) {
            uint4 wv = buf[t * 32 + lane];
            #pragma unroll
            for (int m = 0; m < 4; ++m)
                mma_bf16(c2[m][t], Ah[m][0], Ah[m][1], Ah[m][2], Ah[m][3], wv.x, wv.y);
            #pragma unroll
            for (int m = 0; m < 4; ++m)
                mma_bf16(c2[m][t], Ah[m][0], Ah[m][1], Ah[m][2], Ah[m][3], wv.z, wv.w);
            #pragma unroll
            for (int m = 0; m < 4; ++m)
                mma_bf16(c2[m][t], Al[m][0], Al[m][1], Al[m][2], Al[m][3], wv.x, wv.y);
        }
    }

    // epilogue2: bias + scatter-add
    #pragma unroll
    for (int m = 0; m < 4; ++m) {
        #pragma unroll
        for (int t = 0; t < 2; ++t) {
            int i0 = (w * 2 + t) * 8 + qk * 2;
            int elo = m * 16 + r, ehi = elo + 8;
            float bi0 = b2_all[l * 128 + i0], bi1 = b2_all[l * 128 + i0 + 1];
            int dlo = dst_s[elo], dhi = dst_s[ehi];
            atomicAdd(&d_aggr[dlo * HID + i0],     c2[m][t][0] + bi0);
            atomicAdd(&d_aggr[dlo * HID + i0 + 1], c2[m][t][1] + bi1);
            atomicAdd(&d_aggr[dhi * HID + i0],     c2[m][t][2] + bi0);
            atomicAdd(&d_aggr[dhi * HID + i0 + 1], c2[m][t][3] + bi1);
        }
    }
}

// ---------------- gated node update + residual + LN (NB nodes/block) --------
// Also re-zeroes d_aggr for the next layer/replay.
__global__ void __launch_bounds__(HID) node_kernel(
    const float* __restrict__ gb_all,
    const float* __restrict__ lng_all,
    const float* __restrict__ lnb_all,
    int l) {
    __shared__ float hn[NB][HID], an[NB][HID], red[NB][HID];
    int n0 = blockIdx.x * NB;
    int j = threadIdx.x;
    #pragma unroll
    for (int n = 0; n < NB; ++n) {
        hn[n][j] = d_h[(n0 + n) * HID + j];
        an[n][j] = d_aggr[(n0 + n) * HID + j];
        d_aggr[(n0 + n) * HID + j] = 0.f;
    }
    __syncthreads();

    const float* Wg = d_Wgt + l * 256 * HID;
    float g[NB];
    float gb0 = gb_all[l * HID + j];
    #pragma unroll
    for (int n = 0; n < NB; ++n) g[n] = gb0;
    for (int k = 0; k < HID; ++k) {
        float wv = Wg[k * HID + j];
        #pragma unroll
        for (int n = 0; n < NB; ++n) g[n] = fmaf(hn[n][k], wv, g[n]);
    }
    for (int k = 0; k < HID; ++k) {
        float wv = Wg[(HID + k) * HID + j];
        #pragma unroll
        for (int n = 0; n < NB; ++n) g[n] = fmaf(an[n][k], wv, g[n]);
    }

    float t[NB];
    #pragma unroll
    for (int n = 0; n < NB; ++n) {
        float gs = sigmoidf_(g[n]);
        float hnew = gs * an[n][j] + (1.f - gs) * hn[n][j];
        t[n] = hn[n][j] + hnew;
        red[n][j] = t[n];
    }
    __syncthreads();
    #pragma unroll
    for (int s = 64; s > 0; s >>= 1) {
        if (j < s)
            #pragma unroll
            for (int n = 0; n < NB; ++n) red[n][j] += red[n][j + s];
        __syncthreads();
    }
    float mean[NB];
    #pragma unroll
    for (int n = 0; n < NB; ++n) mean[n] = red[n][0] * (1.f / HID);
    __syncthreads();
    float dd[NB];
    #pragma unroll
    for (int n = 0; n < NB; ++n) { dd[n] = t[n] - mean[n]; red[n][j] = dd[n] * dd[n]; }
    __syncthreads();
    #pragma unroll
    for (int s = 64; s > 0; s >>= 1) {
        if (j < s)
            #pragma unroll
            for (int n = 0; n < NB; ++n) red[n][j] += red[n][j + s];
        __syncthreads();
    }
    float lg = lng_all[l * HID + j], lb = lnb_all[l * HID + j];
    #pragma unroll
    for (int n = 0; n < NB; ++n) {
        float var = red[n][0] * (1.f / HID);
        d_h[(n0 + n) * HID + j] = dd[n] * rsqrtf(var + 1e-5f) * lg + lb;
    }
}

// ---------------- pooling ----------------
__global__ void pool_kernel(const int* __restrict__ batch) {
    int n = blockIdx.x;
    int j = threadIdx.x;
    int g = batch[n];
    atomicAdd(&d_sums[g * HID + j], d_h[n * HID + j]);
    if (j == 0) atomicAdd(&d_counts[g], 1.f);
}

// ---------------- x_global + projector ----------------
__global__ void final_kernel(const float* __restrict__ W1, const float* __restrict__ b1,
                             const float* __restrict__ g1, const float* __restrict__ bb1,
                             const float* __restrict__ W2, const float* __restrict__ b2,
                             const float* __restrict__ g2, const float* __restrict__ bb2,
                             float* __restrict__ out) {
    __shared__ float xg[HID], p[HID], red[HID];
    int gr = blockIdx.x;
    int j = threadIdx.x;

    float c = d_counts[gr];
    float scale = 1.f / fmaxf(c, 1.f) + 1.f / (c + 1e-6f);
    float v = d_sums[gr * HID + j] * scale;
    xg[j] = v;
    out[N_GRAPHS * LAT + gr * HID + j] = v;
    __syncthreads();

    float a = b1[j];
    #pragma unroll 4
    for (int k = 0; k < HID; ++k) a = fmaf(xg[k], W1[j * HID + k], a);
    float m = block_sum128(a, red, j) * (1.f / HID);
    float d = a - m;
    float var = block_sum128(d * d, red, j) * (1.f / HID);
    a = d * rsqrtf(var + 1e-5f) * g1[j] + bb1[j];
    a = a * sigmoidf_(a);
    p[j] = a;
    __syncthreads();

    float z = 0.f;
    if (j < LAT) {
        z = b2[j];
        #pragma unroll 4
        for (int k = 0; k < HID; ++k) z = fmaf(p[k], W2[j * HID + k], z);
    }
    float m2 = block_sum128((j < LAT) ? z : 0.f, red, j) * (1.f / LAT);
    float d2 = z - m2;
    float var2 = block_sum128((j < LAT) ? d2 * d2 : 0.f, red, j) * (1.f / LAT);
    if (j < LAT)
        out[gr * LAT + j] = d2 * rsqrtf(var2 + 1e-5f) * g2[j] + bb2[j];
}

// ---------------- launch ----------------
extern "C" void kernel_launch(void* const* d_in, const int* in_sizes, int n_in,
                              void* d_out, int out_size) {
    const float* x     = (const float*)d_in[0];
    const float* ea    = (const float*)d_in[1];
    const int*   ei    = (const int*)  d_in[2];
    const int*   batch = (const int*)  d_in[3];
    const float* embW  = (const float*)d_in[4];
    const float* embb  = (const float*)d_in[5];
    const float* embg  = (const float*)d_in[6];
    const float* emblb = (const float*)d_in[7];
    const float* m1W   = (const float*)d_in[8];
    const float* m1b   = (const float*)d_in[9];
    const float* m2W   = (const float*)d_in[10];
    const float* m2b   = (const float*)d_in[11];
    const float* gW    = (const float*)d_in[12];
    const float* gb    = (const float*)d_in[13];
    const float* lng   = (const float*)d_in[14];
    const float* lnb   = (const float*)d_in[15];
    const float* p1W   = (const float*)d_in[16];
    const float* p1b   = (const float*)d_in[17];
    const float* pl1g  = (const float*)d_in[18];
    const float* pl1b  = (const float*)d_in[19];
    const float* p2W   = (const float*)d_in[20];
    const float* p2b   = (const float*)d_in[21];
    const float* pl2g  = (const float*)d_in[22];
    const float* pl2b  = (const float*)d_in[23];
    float* out = (float*)d_out;

    // smem: Zh+Zl (67584) + idx/ea (768) + per-warp weight stages (32768) = 101120
    const int smem_bytes = 2 * 64 * 132 * 4 + 3 * 64 * 4 + 2048 * 16;
    cudaFuncSetAttribute(edge_kernel, cudaFuncAttributeMaxDynamicSharedMemorySize, smem_bytes);

    pack_kernel<<<384, 256>>>(m1W, m2W, gW);
    embed_kernel<<<N_NODES, HID>>>(x, embW, embb, embg, emblb);

    for (int l = 0; l < NLAY; ++l) {
        edge_kernel<<<N_EDGES / ET, 256, smem_bytes>>>(ea, ei, m1b, m2b, l);
        node_kernel<<<N_NODES / NB, HID>>>(gb, lng, lnb, l);
    }

    zero_pool_kernel<<<33, 256>>>();
    pool_kernel<<<N_NODES, HID>>>(batch);
    final_kernel<<<N_GRAPHS, HID>>>(p1W, p1b, pl1g, pl1b, p2W, p2b, pl2g, pl2b, out);
}

// round 13
// speedup vs baseline: 1.1922x; 1.0757x over previous
#include <cuda_runtime.h>
#include <cuda_bf16.h>
#include <math.h>

#define N_NODES 10000
#define N_EDGES 160000
#define N_GRAPHS 64
#define HID 128
#define LAT 64
#define NLAY 3
#define ET 64          // edges per block in the edge kernel
#define NB 16          // nodes per block in node_kernel

// ---------------- device scratch (no allocations allowed) ----------------
__device__ float d_h[N_NODES * HID];
__device__ float d_aggr[N_NODES * HID];   // zero at load; node_kernel re-zeros after reading
// B-fragment packed weights: per (layer, kstep, ntile, lane) a uint4 {hi01, hi89, lo01, lo89}
__device__ uint4 d_W1f[NLAY * 16 * 32 * 32];   // GEMM1: K=256 (16 steps), N=256 (32 ntiles)
__device__ uint4 d_W2f[NLAY * 16 * 16 * 32];   // GEMM2: K=256 (16 steps), N=128 (16 ntiles)
__device__ float d_W1tail[NLAY * 256];         // k=256 column (edge_attr weight)
__device__ float4 d_Wg4[NLAY * 64 * HID];      // gate_W k-quad packed: [l][kq(64)][j(128)] = W[j][4kq..4kq+3]
__device__ float d_sums[N_GRAPHS * HID];
__device__ float d_counts[N_GRAPHS];

__device__ __forceinline__ float sigmoidf_(float v) {
    return 1.f / (1.f + __expf(-v));
}
__device__ __forceinline__ unsigned pk2(float lo, float hi) {
    unsigned r;
    asm("cvt.rn.bf16x2.f32 %0, %1, %2;" : "=r"(r) : "f"(hi), "f"(lo));
    return r;
}
__device__ __forceinline__ void mma_bf16(float c[4],
                                         unsigned a0, unsigned a1, unsigned a2, unsigned a3,
                                         unsigned b0, unsigned b1) {
    asm("mma.sync.aligned.m16n8k16.row.col.f32.bf16.bf16.f32 "
        "{%0,%1,%2,%3}, {%4,%5,%6,%7}, {%8,%9}, {%0,%1,%2,%3};"
        : "+f"(c[0]), "+f"(c[1]), "+f"(c[2]), "+f"(c[3])
        : "r"(a0), "r"(a1), "r"(a2), "r"(a3), "r"(b0), "r"(b1));
}
__device__ __forceinline__ void ldsm4(unsigned r[4], unsigned addr) {
    asm volatile("ldmatrix.sync.aligned.m8n8.x4.shared.b16 {%0,%1,%2,%3}, [%4];"
        : "=r"(r[0]), "=r"(r[1]), "=r"(r[2]), "=r"(r[3]) : "r"(addr));
}

__device__ __forceinline__ float block_sum128(float v, float* red, int j) {
    red[j] = v;
    __syncthreads();
    #pragma unroll
    for (int s = 64; s > 0; s >>= 1) {
        if (j < s) red[j] += red[j + s];
        __syncthreads();
    }
    float r = red[0];
    __syncthreads();
    return r;
}

// ---------------- weight fragment packing (run once per launch) ----------------
__global__ void pack_kernel(const float* __restrict__ W1,   // [3][256][257]
                            const float* __restrict__ W2,   // [3][128][256]
                            const float* __restrict__ Wg) { // [3][128][256]
    int idx = blockIdx.x * blockDim.x + threadIdx.x;
    int stride = gridDim.x * blockDim.x;
    const int n1 = NLAY * 16 * 32 * 32;
    for (int t = idx; t < n1; t += stride) {
        int l = t / (16 * 32 * 32);
        int r = t % (16 * 32 * 32);
        int s = r / (32 * 32);
        int r2 = r % (32 * 32);
        int tt = r2 / 32;
        int lane = r2 % 32;
        int n = tt * 8 + lane / 4;
        int k0 = s * 16 + (lane % 4) * 2;
        const float* row = W1 + (l * 256 + n) * 257;
        float f0 = row[k0], f1 = row[k0 + 1], f2 = row[k0 + 8], f3 = row[k0 + 9];
        unsigned h01 = pk2(f0, f1);
        unsigned h89 = pk2(f2, f3);
        float a0 = __uint_as_float(h01 << 16), a1 = __uint_as_float(h01 & 0xFFFF0000u);
        float a2 = __uint_as_float(h89 << 16), a3 = __uint_as_float(h89 & 0xFFFF0000u);
        uint4 o;
        o.x = h01; o.y = h89;
        o.z = pk2(f0 - a0, f1 - a1);
        o.w = pk2(f2 - a2, f3 - a3);
        d_W1f[t] = o;
    }
    const int n2 = NLAY * 16 * 16 * 32;
    for (int t = idx; t < n2; t += stride) {
        int l = t / (16 * 16 * 32);
        int r = t % (16 * 16 * 32);
        int s = r / (16 * 32);
        int r2 = r % (16 * 32);
        int tt = r2 / 32;
        int lane = r2 % 32;
        int n = tt * 8 + lane / 4;
        int k0 = s * 16 + (lane % 4) * 2;
        const float* row = W2 + (l * 128 + n) * 256;
        float f0 = row[k0], f1 = row[k0 + 1], f2 = row[k0 + 8], f3 = row[k0 + 9];
        unsigned h01 = pk2(f0, f1);
        unsigned h89 = pk2(f2, f3);
        float a0 = __uint_as_float(h01 << 16), a1 = __uint_as_float(h01 & 0xFFFF0000u);
        float a2 = __uint_as_float(h89 << 16), a3 = __uint_as_float(h89 & 0xFFFF0000u);
        uint4 o;
        o.x = h01; o.y = h89;
        o.z = pk2(f0 - a0, f1 - a1);
        o.w = pk2(f2 - a2, f3 - a3);
        d_W2f[t] = o;
    }
    for (int t = idx; t < NLAY * 256; t += stride) {
        int l = t / 256;
        int j = t % 256;
        d_W1tail[t] = W1[(l * 256 + j) * 257 + 256];
    }
    // gate weights: k-quad pack  d_Wg4[l][kq][j] = Wg[l][j][4kq .. 4kq+3]
    const int n3 = NLAY * 64 * HID;
    for (int t = idx; t < n3; t += stride) {
        int l = t / (64 * HID);
        int r = t % (64 * HID);
        int kq = r / HID;
        int j = r % HID;
        const float* src = Wg + (l * HID + j) * 256 + kq * 4;
        d_Wg4[t] = make_float4(src[0], src[1], src[2], src[3]);
    }
}

// ---------------- node embedding ----------------
__global__ void embed_kernel(const float* __restrict__ x,
                             const float* __restrict__ W,
                             const float* __restrict__ b,
                             const float* __restrict__ lng,
                             const float* __restrict__ lnb) {
    __shared__ float red[HID];
    int n = blockIdx.x;
    int j = threadIdx.x;
    float x0 = x[n * 3 + 0], x1 = x[n * 3 + 1], x2 = x[n * 3 + 2];
    float v = b[j] + x0 * W[j * 3 + 0] + x1 * W[j * 3 + 1] + x2 * W[j * 3 + 2];
    float m = block_sum128(v, red, j) * (1.f / HID);
    float d = v - m;
    float var = block_sum128(d * d, red, j) * (1.f / HID);
    float y = d * rsqrtf(var + 1e-5f) * lng[j] + lnb[j];
    d_h[n * HID + j] = y * sigmoidf_(y);
}

__global__ void zero_pool_kernel() {
    int idx = blockIdx.x * blockDim.x + threadIdx.x;
    if (idx < N_GRAPHS * HID) d_sums[idx] = 0.f;
    if (idx < N_GRAPHS) d_counts[idx] = 0.f;
}

// ---------------- edge MLP via tensor cores (split-bf16 3-term, LDSM feeds) ----
// Byte-exact R7 structure: direct per-warp LDG of weight fragments inside the
// t-loop; __launch_bounds__(256, 2) caps regs at 128 -> 2 CTAs/SM.
__global__ void __launch_bounds__(256, 2) edge_kernel(
    const float* __restrict__ edge_attr,
    const int* __restrict__ edge_index,
    const float* __restrict__ b1_all,   // [3][256]
    const float* __restrict__ b2_all,   // [3][128]
    int l) {
    extern __shared__ __align__(16) unsigned sm[];
    unsigned* Zh = sm;                      // 64*132 words
    unsigned* Zl = sm + 64 * 132;
    int* dst_s = (int*)(sm + 2 * 64 * 132);
    int* src_s = dst_s + 64;
    float* ea_s = (float*)(src_s + 64);

    const int tid = threadIdx.x;
    const int lane = tid & 31, w = tid >> 5;
    const int e0 = blockIdx.x * ET;

    if (tid < 64) { dst_s[tid] = edge_index[N_EDGES + e0 + tid]; ea_s[tid] = edge_attr[e0 + tid]; }
    else if (tid < 128) src_s[tid - 64] = edge_index[e0 + tid - 64];
    __syncthreads();

    // gather + fp32 -> bf16 hi/lo conversion
    {
        int e = tid >> 2, q = tid & 3;
        int node = (q < 2) ? dst_s[e] : src_s[e];
        const float4* hp = (const float4*)(d_h + node * HID + (q & 1) * 64);
        unsigned* oh = Zh + e * 132 + q * 32;
        unsigned* ol = Zl + e * 132 + q * 32;
        #pragma unroll
        for (int i = 0; i < 16; ++i) {
            float4 v = hp[i];
            unsigned h0 = pk2(v.x, v.y), h1 = pk2(v.z, v.w);
            float a0 = __uint_as_float(h0 << 16), a1 = __uint_as_float(h0 & 0xFFFF0000u);
            float a2 = __uint_as_float(h1 << 16), a3 = __uint_as_float(h1 & 0xFFFF0000u);
            oh[i * 2] = h0; oh[i * 2 + 1] = h1;
            ol[i * 2] = pk2(v.x - a0, v.y - a1);
            ol[i * 2 + 1] = pk2(v.z - a2, v.w - a3);
        }
    }
    __syncthreads();

    const int r = lane >> 2, qk = lane & 3;
    const unsigned zh_base = (unsigned)__cvta_generic_to_shared(Zh);
    const unsigned zl_base = (unsigned)__cvta_generic_to_shared(Zl);
    const unsigned aoff = ((lane & 15) * 132 + ((lane >> 4) << 2)) * 4;

    // ---- GEMM1 ----
    float c[4][4][4];
    #pragma unroll
    for (int m = 0; m < 4; ++m)
        #pragma unroll
        for (int t = 0; t < 4; ++t)
            #pragma unroll
            for (int k = 0; k < 4; ++k) c[m][t][k] = 0.f;

    for (int s = 0; s < 16; ++s) {
        unsigned Ah[4][4], Al[4][4];
        #pragma unroll
        for (int m = 0; m < 4; ++m) {
            unsigned toff = aoff + (m * 16 * 132 + s * 8) * 4;
            ldsm4(Ah[m], zh_base + toff);
            ldsm4(Al[m], zl_base + toff);
        }
        #pragma unroll
        for (int t = 0; t < 4; ++t) {
            uint4 wv = d_W1f[((l * 16 + s) * 32 + (w * 4 + t)) * 32 + lane];
            #pragma unroll
            for (int m = 0; m < 4; ++m)
                mma_bf16(c[m][t], Ah[m][0], Ah[m][1], Ah[m][2], Ah[m][3], wv.x, wv.y);
            #pragma unroll
            for (int m = 0; m < 4; ++m)
                mma_bf16(c[m][t], Ah[m][0], Ah[m][1], Ah[m][2], Ah[m][3], wv.z, wv.w);
            #pragma unroll
            for (int m = 0; m < 4; ++m)
                mma_bf16(c[m][t], Al[m][0], Al[m][1], Al[m][2], Al[m][3], wv.x, wv.y);
        }
    }
    __syncthreads();   // all Z reads complete before overwrite

    // epilogue1: bias + edge_attr tail + silu -> bf16 hi/lo back into Zh/Zl
    #pragma unroll
    for (int m = 0; m < 4; ++m) {
        #pragma unroll
        for (int t = 0; t < 4; ++t) {
            int n0 = (w * 4 + t) * 8 + qk * 2;
            int elo = m * 16 + r, ehi = elo + 8;
            float bn0 = b1_all[l * 256 + n0], bn1 = b1_all[l * 256 + n0 + 1];
            float wt0 = d_W1tail[l * 256 + n0], wt1 = d_W1tail[l * 256 + n0 + 1];
            float el = ea_s[elo], eh = ea_s[ehi];
            float v00 = c[m][t][0] + bn0 + el * wt0;
            float v01 = c[m][t][1] + bn1 + el * wt1;
            float v10 = c[m][t][2] + bn0 + eh * wt0;
            float v11 = c[m][t][3] + bn1 + eh * wt1;
            v00 *= sigmoidf_(v00); v01 *= sigmoidf_(v01);
            v10 *= sigmoidf_(v10); v11 *= sigmoidf_(v11);
            int wlo = elo * 132 + (w * 4 + t) * 4 + qk;
            int whi = ehi * 132 + (w * 4 + t) * 4 + qk;
            unsigned h0 = pk2(v00, v01);
            unsigned h1 = pk2(v10, v11);
            float a0 = __uint_as_float(h0 << 16), a1 = __uint_as_float(h0 & 0xFFFF0000u);
            float a2 = __uint_as_float(h1 << 16), a3 = __uint_as_float(h1 & 0xFFFF0000u);
            Zh[wlo] = h0; Zl[wlo] = pk2(v00 - a0, v01 - a1);
            Zh[whi] = h1; Zl[whi] = pk2(v10 - a2, v11 - a3);
        }
    }
    __syncthreads();

    // ---- GEMM2 ----
    float c2[4][2][4];
    #pragma unroll
    for (int m = 0; m < 4; ++m)
        #pragma unroll
        for (int t = 0; t < 2; ++t)
            #pragma unroll
            for (int k = 0; k < 4; ++k) c2[m][t][k] = 0.f;

    for (int s = 0; s < 16; ++s) {
        unsigned Ah[4][4], Al[4][4];
        #pragma unroll
        for (int m = 0; m < 4; ++m) {
            unsigned toff = aoff + (m * 16 * 132 + s * 8) * 4;
            ldsm4(Ah[m], zh_base + toff);
            ldsm4(Al[m], zl_base + toff);
        }
        #pragma unroll
        for (int t = 0; t < 2; ++t) {
            uint4 wv = d_W2f[((l * 16 + s) * 16 + (w * 2 + t)) * 32 + lane];
            #pragma unroll
            for (int m = 0; m < 4; ++m)
                mma_bf16(c2[m][t], Ah[m][0], Ah[m][1], Ah[m][2], Ah[m][3], wv.x, wv.y);
            #pragma unroll
            for (int m = 0; m < 4; ++m)
                mma_bf16(c2[m][t], Ah[m][0], Ah[m][1], Ah[m][2], Ah[m][3], wv.z, wv.w);
            #pragma unroll
            for (int m = 0; m < 4; ++m)
                mma_bf16(c2[m][t], Al[m][0], Al[m][1], Al[m][2], Al[m][3], wv.x, wv.y);
        }
    }

    // epilogue2: bias + scatter-add
    #pragma unroll
    for (int m = 0; m < 4; ++m) {
        #pragma unroll
        for (int t = 0; t < 2; ++t) {
            int i0 = (w * 2 + t) * 8 + qk * 2;
            int elo = m * 16 + r, ehi = elo + 8;
            float bi0 = b2_all[l * 128 + i0], bi1 = b2_all[l * 128 + i0 + 1];
            int dlo = dst_s[elo], dhi = dst_s[ehi];
            atomicAdd(&d_aggr[dlo * HID + i0],     c2[m][t][0] + bi0);
            atomicAdd(&d_aggr[dlo * HID + i0 + 1], c2[m][t][1] + bi1);
            atomicAdd(&d_aggr[dhi * HID + i0],     c2[m][t][2] + bi0);
            atomicAdd(&d_aggr[dhi * HID + i0 + 1], c2[m][t][3] + bi1);
        }
    }
}

// ---------------- gated node update + residual + LN (NB=16 nodes/block) -----
// float4 k-quad gate weights: one LDG.128 feeds 64 FMA. Re-zeros d_aggr.
__global__ void __launch_bounds__(HID) node_kernel(
    const float* __restrict__ gb_all,
    const float* __restrict__ lng_all,
    const float* __restrict__ lnb_all,
    int l) {
    __shared__ float hn[NB][HID], an[NB][HID], red[NB][HID];
    int n0 = blockIdx.x * NB;
    int j = threadIdx.x;
    #pragma unroll
    for (int n = 0; n < NB; ++n) {
        hn[n][j] = d_h[(n0 + n) * HID + j];
        an[n][j] = d_aggr[(n0 + n) * HID + j];
        d_aggr[(n0 + n) * HID + j] = 0.f;
    }
    __syncthreads();

    const float4* Wg4 = d_Wg4 + l * 64 * HID;
    float g[NB];
    float gb0 = gb_all[l * HID + j];
    #pragma unroll
    for (int n = 0; n < NB; ++n) g[n] = gb0;
    // k in [0,128): hn
    for (int kq = 0; kq < 32; ++kq) {
        float4 wv = Wg4[kq * HID + j];
        const int k0 = kq * 4;
        #pragma unroll
        for (int n = 0; n < NB; ++n) {
            g[n] = fmaf(hn[n][k0 + 0], wv.x, g[n]);
            g[n] = fmaf(hn[n][k0 + 1], wv.y, g[n]);
            g[n] = fmaf(hn[n][k0 + 2], wv.z, g[n]);
            g[n] = fmaf(hn[n][k0 + 3], wv.w, g[n]);
        }
    }
    // k in [128,256): an
    for (int kq = 32; kq < 64; ++kq) {
        float4 wv = Wg4[kq * HID + j];
        const int k0 = (kq - 32) * 4;
        #pragma unroll
        for (int n = 0; n < NB; ++n) {
            g[n] = fmaf(an[n][k0 + 0], wv.x, g[n]);
            g[n] = fmaf(an[n][k0 + 1], wv.y, g[n]);
            g[n] = fmaf(an[n][k0 + 2], wv.z, g[n]);
            g[n] = fmaf(an[n][k0 + 3], wv.w, g[n]);
        }
    }

    float t[NB];
    #pragma unroll
    for (int n = 0; n < NB; ++n) {
        float gs = sigmoidf_(g[n]);
        float hnew = gs * an[n][j] + (1.f - gs) * hn[n][j];
        t[n] = hn[n][j] + hnew;
        red[n][j] = t[n];
    }
    __syncthreads();
    #pragma unroll
    for (int s = 64; s > 0; s >>= 1) {
        if (j < s)
            #pragma unroll
            for (int n = 0; n < NB; ++n) red[n][j] += red[n][j + s];
        __syncthreads();
    }
    float mean[NB];
    #pragma unroll
    for (int n = 0; n < NB; ++n) mean[n] = red[n][0] * (1.f / HID);
    __syncthreads();
    float dd[NB];
    #pragma unroll
    for (int n = 0; n < NB; ++n) { dd[n] = t[n] - mean[n]; red[n][j] = dd[n] * dd[n]; }
    __syncthreads();
    #pragma unroll
    for (int s = 64; s > 0; s >>= 1) {
        if (j < s)
            #pragma unroll
            for (int n = 0; n < NB; ++n) red[n][j] += red[n][j + s];
        __syncthreads();
    }
    float lg = lng_all[l * HID + j], lb = lnb_all[l * HID + j];
    #pragma unroll
    for (int n = 0; n < NB; ++n) {
        float var = red[n][0] * (1.f / HID);
        d_h[(n0 + n) * HID + j] = dd[n] * rsqrtf(var + 1e-5f) * lg + lb;
    }
}

// ---------------- pooling ----------------
__global__ void pool_kernel(const int* __restrict__ batch) {
    int n = blockIdx.x;
    int j = threadIdx.x;
    int g = batch[n];
    atomicAdd(&d_sums[g * HID + j], d_h[n * HID + j]);
    if (j == 0) atomicAdd(&d_counts[g], 1.f);
}

// ---------------- x_global + projector ----------------
__global__ void final_kernel(const float* __restrict__ W1, const float* __restrict__ b1,
                             const float* __restrict__ g1, const float* __restrict__ bb1,
                             const float* __restrict__ W2, const float* __restrict__ b2,
                             const float* __restrict__ g2, const float* __restrict__ bb2,
                             float* __restrict__ out) {
    __shared__ float xg[HID], p[HID], red[HID];
    int gr = blockIdx.x;
    int j = threadIdx.x;

    float c = d_counts[gr];
    float scale = 1.f / fmaxf(c, 1.f) + 1.f / (c + 1e-6f);
    float v = d_sums[gr * HID + j] * scale;
    xg[j] = v;
    out[N_GRAPHS * LAT + gr * HID + j] = v;
    __syncthreads();

    float a = b1[j];
    #pragma unroll 4
    for (int k = 0; k < HID; ++k) a = fmaf(xg[k], W1[j * HID + k], a);
    float m = block_sum128(a, red, j) * (1.f / HID);
    float d = a - m;
    float var = block_sum128(d * d, red, j) * (1.f / HID);
    a = d * rsqrtf(var + 1e-5f) * g1[j] + bb1[j];
    a = a * sigmoidf_(a);
    p[j] = a;
    __syncthreads();

    float z = 0.f;
    if (j < LAT) {
        z = b2[j];
        #pragma unroll 4
        for (int k = 0; k < HID; ++k) z = fmaf(p[k], W2[j * HID + k], z);
    }
    float m2 = block_sum128((j < LAT) ? z : 0.f, red, j) * (1.f / LAT);
    float d2 = z - m2;
    float var2 = block_sum128((j < LAT) ? d2 * d2 : 0.f, red, j) * (1.f / LAT);
    if (j < LAT)
        out[gr * LAT + j] = d2 * rsqrtf(var2 + 1e-5f) * g2[j] + bb2[j];
}

// ---------------- launch ----------------
extern "C" void kernel_launch(void* const* d_in, const int* in_sizes, int n_in,
                              void* d_out, int out_size) {
    const float* x     = (const float*)d_in[0];
    const float* ea    = (const float*)d_in[1];
    const int*   ei    = (const int*)  d_in[2];
    const int*   batch = (const int*)  d_in[3];
    const float* embW  = (const float*)d_in[4];
    const float* embb  = (const float*)d_in[5];
    const float* embg  = (const float*)d_in[6];
    const float* emblb = (const float*)d_in[7];
    const float* m1W   = (const float*)d_in[8];
    const float* m1b   = (const float*)d_in[9];
    const float* m2W   = (const float*)d_in[10];
    const float* m2b   = (const float*)d_in[11];
    const float* gW    = (const float*)d_in[12];
    const float* gb    = (const float*)d_in[13];
    const float* lng   = (const float*)d_in[14];
    const float* lnb   = (const float*)d_in[15];
    const float* p1W   = (const float*)d_in[16];
    const float* p1b   = (const float*)d_in[17];
    const float* pl1g  = (const float*)d_in[18];
    const float* pl1b  = (const float*)d_in[19];
    const float* p2W   = (const float*)d_in[20];
    const float* p2b   = (const float*)d_in[21];
    const float* pl2g  = (const float*)d_in[22];
    const float* pl2b  = (const float*)d_in[23];
    float* out = (float*)d_out;

    const int smem_bytes = 2 * 64 * 132 * 4 + 3 * 64 * 4;   // 68352
    cudaFuncSetAttribute(edge_kernel, cudaFuncAttributeMaxDynamicSharedMemorySize, smem_bytes);

    pack_kernel<<<384, 256>>>(m1W, m2W, gW);
    embed_kernel<<<N_NODES, HID>>>(x, embW, embb, embg, emblb);

    for (int l = 0; l < NLAY; ++l) {
        edge_kernel<<<N_EDGES / ET, 256, smem_bytes>>>(ea, ei, m1b, m2b, l);
        node_kernel<<<N_NODES / NB, HID>>>(gb, lng, lnb, l);
    }

    zero_pool_kernel<<<33, 256>>>();
    pool_kernel<<<N_NODES, HID>>>(batch);
    final_kernel<<<N_GRAPHS, HID>>>(p1W, p1b, pl1g, pl1b, p2W, p2b, pl2g, pl2b, out);
}

// round 15
// speedup vs baseline: 1.1930x; 1.0007x over previous
#include <cuda_runtime.h>
#include <cuda_bf16.h>
#include <math.h>

#define N_NODES 10000
#define N_EDGES 160000
#define N_GRAPHS 64
#define HID 128
#define LAT 64
#define NLAY 3
#define ET 64          // edges per block in the edge kernel
#define NB 8           // nodes per block in node_kernel

// ---------------- device scratch (no allocations allowed) ----------------
__device__ float d_h[N_NODES * HID];
__device__ float d_aggr[N_NODES * HID];   // zero at load; node_kernel re-zeros after reading
// B-fragment packed weights: per (layer, kstep, ntile, lane) a uint4 {hi01, hi89, lo01, lo89}
__device__ uint4 d_W1f[NLAY * 16 * 32 * 32];   // GEMM1: K=256 (16 steps), N=256 (32 ntiles)
__device__ uint4 d_W2f[NLAY * 16 * 16 * 32];   // GEMM2: K=256 (16 steps), N=128 (16 ntiles)
__device__ float d_W1tail[NLAY * 256];         // k=256 column (edge_attr weight)
__device__ float4 d_Wg4[NLAY * 64 * HID];      // gate_W k-quad packed: [l][kq(64)][j(128)] = W[j][4kq..4kq+3]
__device__ float d_sums[N_GRAPHS * HID];
__device__ float d_counts[N_GRAPHS];

__device__ __forceinline__ float sigmoidf_(float v) {
    return 1.f / (1.f + __expf(-v));
}
__device__ __forceinline__ unsigned pk2(float lo, float hi) {
    unsigned r;
    asm("cvt.rn.bf16x2.f32 %0, %1, %2;" : "=r"(r) : "f"(hi), "f"(lo));
    return r;
}
__device__ __forceinline__ void mma_bf16(float c[4],
                                         unsigned a0, unsigned a1, unsigned a2, unsigned a3,
                                         unsigned b0, unsigned b1) {
    asm("mma.sync.aligned.m16n8k16.row.col.f32.bf16.bf16.f32 "
        "{%0,%1,%2,%3}, {%4,%5,%6,%7}, {%8,%9}, {%0,%1,%2,%3};"
        : "+f"(c[0]), "+f"(c[1]), "+f"(c[2]), "+f"(c[3])
        : "r"(a0), "r"(a1), "r"(a2), "r"(a3), "r"(b0), "r"(b1));
}
__device__ __forceinline__ void ldsm4(unsigned r[4], unsigned addr) {
    asm volatile("ldmatrix.sync.aligned.m8n8.x4.shared.b16 {%0,%1,%2,%3}, [%4];"
        : "=r"(r[0]), "=r"(r[1]), "=r"(r[2]), "=r"(r[3]) : "r"(addr));
}

__device__ __forceinline__ float block_sum128(float v, float* red, int j) {
    red[j] = v;
    __syncthreads();
    #pragma unroll
    for (int s = 64; s > 0; s >>= 1) {
        if (j < s) red[j] += red[j + s];
        __syncthreads();
    }
    float r = red[0];
    __syncthreads();
    return r;
}

// ---------------- weight fragment packing (run once per launch) ----------------
__global__ void pack_kernel(const float* __restrict__ W1,   // [3][256][257]
                            const float* __restrict__ W2,   // [3][128][256]
                            const float* __restrict__ Wg) { // [3][128][256]
    int idx = blockIdx.x * blockDim.x + threadIdx.x;
    int stride = gridDim.x * blockDim.x;
    const int n1 = NLAY * 16 * 32 * 32;
    for (int t = idx; t < n1; t += stride) {
        int l = t / (16 * 32 * 32);
        int r = t % (16 * 32 * 32);
        int s = r / (32 * 32);
        int r2 = r % (32 * 32);
        int tt = r2 / 32;
        int lane = r2 % 32;
        int n = tt * 8 + lane / 4;
        int k0 = s * 16 + (lane % 4) * 2;
        const float* row = W1 + (l * 256 + n) * 257;
        float f0 = row[k0], f1 = row[k0 + 1], f2 = row[k0 + 8], f3 = row[k0 + 9];
        unsigned h01 = pk2(f0, f1);
        unsigned h89 = pk2(f2, f3);
        float a0 = __uint_as_float(h01 << 16), a1 = __uint_as_float(h01 & 0xFFFF0000u);
        float a2 = __uint_as_float(h89 << 16), a3 = __uint_as_float(h89 & 0xFFFF0000u);
        uint4 o;
        o.x = h01; o.y = h89;
        o.z = pk2(f0 - a0, f1 - a1);
        o.w = pk2(f2 - a2, f3 - a3);
        d_W1f[t] = o;
    }
    const int n2 = NLAY * 16 * 16 * 32;
    for (int t = idx; t < n2; t += stride) {
        int l = t / (16 * 16 * 32);
        int r = t % (16 * 16 * 32);
        int s = r / (16 * 32);
        int r2 = r % (16 * 32);
        int tt = r2 / 32;
        int lane = r2 % 32;
        int n = tt * 8 + lane / 4;
        int k0 = s * 16 + (lane % 4) * 2;
        const float* row = W2 + (l * 128 + n) * 256;
        float f0 = row[k0], f1 = row[k0 + 1], f2 = row[k0 + 8], f3 = row[k0 + 9];
        unsigned h01 = pk2(f0, f1);
        unsigned h89 = pk2(f2, f3);
        float a0 = __uint_as_float(h01 << 16), a1 = __uint_as_float(h01 & 0xFFFF0000u);
        float a2 = __uint_as_float(h89 << 16), a3 = __uint_as_float(h89 & 0xFFFF0000u);
        uint4 o;
        o.x = h01; o.y = h89;
        o.z = pk2(f0 - a0, f1 - a1);
        o.w = pk2(f2 - a2, f3 - a3);
        d_W2f[t] = o;
    }
    for (int t = idx; t < NLAY * 256; t += stride) {
        int l = t / 256;
        int j = t % 256;
        d_W1tail[t] = W1[(l * 256 + j) * 257 + 256];
    }
    // gate weights: k-quad pack  d_Wg4[l][kq][j] = Wg[l][j][4kq .. 4kq+3]
    const int n3 = NLAY * 64 * HID;
    for (int t = idx; t < n3; t += stride) {
        int l = t / (64 * HID);
        int r = t % (64 * HID);
        int kq = r / HID;
        int j = r % HID;
        const float* src = Wg + (l * HID + j) * 256 + kq * 4;
        d_Wg4[t] = make_float4(src[0], src[1], src[2], src[3]);
    }
}

// ---------------- node embedding ----------------
__global__ void embed_kernel(const float* __restrict__ x,
                             const float* __restrict__ W,
                             const float* __restrict__ b,
                             const float* __restrict__ lng,
                             const float* __restrict__ lnb) {
    __shared__ float red[HID];
    int n = blockIdx.x;
    int j = threadIdx.x;
    float x0 = x[n * 3 + 0], x1 = x[n * 3 + 1], x2 = x[n * 3 + 2];
    float v = b[j] + x0 * W[j * 3 + 0] + x1 * W[j * 3 + 1] + x2 * W[j * 3 + 2];
    float m = block_sum128(v, red, j) * (1.f / HID);
    float d = v - m;
    float var = block_sum128(d * d, red, j) * (1.f / HID);
    float y = d * rsqrtf(var + 1e-5f) * lng[j] + lnb[j];
    d_h[n * HID + j] = y * sigmoidf_(y);
}

__global__ void zero_pool_kernel() {
    int idx = blockIdx.x * blockDim.x + threadIdx.x;
    if (idx < N_GRAPHS * HID) d_sums[idx] = 0.f;
    if (idx < N_GRAPHS) d_counts[idx] = 0.f;
}

// ---------------- edge MLP via tensor cores (split-bf16 3-term, LDSM feeds) ----
// Byte-exact R7 structure: direct per-warp LDG of weight fragments inside the
// t-loop; __launch_bounds__(256, 2) caps regs at 128 -> 2 CTAs/SM.
__global__ void __launch_bounds__(256, 2) edge_kernel(
    const float* __restrict__ edge_attr,
    const int* __restrict__ edge_index,
    const float* __restrict__ b1_all,   // [3][256]
    const float* __restrict__ b2_all,   // [3][128]
    int l) {
    extern __shared__ __align__(16) unsigned sm[];
    unsigned* Zh = sm;                      // 64*132 words
    unsigned* Zl = sm + 64 * 132;
    int* dst_s = (int*)(sm + 2 * 64 * 132);
    int* src_s = dst_s + 64;
    float* ea_s = (float*)(src_s + 64);

    const int tid = threadIdx.x;
    const int lane = tid & 31, w = tid >> 5;
    const int e0 = blockIdx.x * ET;

    if (tid < 64) { dst_s[tid] = edge_index[N_EDGES + e0 + tid]; ea_s[tid] = edge_attr[e0 + tid]; }
    else if (tid < 128) src_s[tid - 64] = edge_index[e0 + tid - 64];
    __syncthreads();

    // gather + fp32 -> bf16 hi/lo conversion
    {
        int e = tid >> 2, q = tid & 3;
        int node = (q < 2) ? dst_s[e] : src_s[e];
        const float4* hp = (const float4*)(d_h + node * HID + (q & 1) * 64);
        unsigned* oh = Zh + e * 132 + q * 32;
        unsigned* ol = Zl + e * 132 + q * 32;
        #pragma unroll
        for (int i = 0; i < 16; ++i) {
            float4 v = hp[i];
            unsigned h0 = pk2(v.x, v.y), h1 = pk2(v.z, v.w);
            float a0 = __uint_as_float(h0 << 16), a1 = __uint_as_float(h0 & 0xFFFF0000u);
            float a2 = __uint_as_float(h1 << 16), a3 = __uint_as_float(h1 & 0xFFFF0000u);
            oh[i * 2] = h0; oh[i * 2 + 1] = h1;
            ol[i * 2] = pk2(v.x - a0, v.y - a1);
            ol[i * 2 + 1] = pk2(v.z - a2, v.w - a3);
        }
    }
    __syncthreads();

    const int r = lane >> 2, qk = lane & 3;
    const unsigned zh_base = (unsigned)__cvta_generic_to_shared(Zh);
    const unsigned zl_base = (unsigned)__cvta_generic_to_shared(Zl);
    const unsigned aoff = ((lane & 15) * 132 + ((lane >> 4) << 2)) * 4;

    // ---- GEMM1 ----
    float c[4][4][4];
    #pragma unroll
    for (int m = 0; m < 4; ++m)
        #pragma unroll
        for (int t = 0; t < 4; ++t)
            #pragma unroll
            for (int k = 0; k < 4; ++k) c[m][t][k] = 0.f;

    for (int s = 0; s < 16; ++s) {
        unsigned Ah[4][4], Al[4][4];
        #pragma unroll
        for (int m = 0; m < 4; ++m) {
            unsigned toff = aoff + (m * 16 * 132 + s * 8) * 4;
            ldsm4(Ah[m], zh_base + toff);
            ldsm4(Al[m], zl_base + toff);
        }
        #pragma unroll
        for (int t = 0; t < 4; ++t) {
            uint4 wv = d_W1f[((l * 16 + s) * 32 + (w * 4 + t)) * 32 + lane];
            #pragma unroll
            for (int m = 0; m < 4; ++m)
                mma_bf16(c[m][t], Ah[m][0], Ah[m][1], Ah[m][2], Ah[m][3], wv.x, wv.y);
            #pragma unroll
            for (int m = 0; m < 4; ++m)
                mma_bf16(c[m][t], Ah[m][0], Ah[m][1], Ah[m][2], Ah[m][3], wv.z, wv.w);
            #pragma unroll
            for (int m = 0; m < 4; ++m)
                mma_bf16(c[m][t], Al[m][0], Al[m][1], Al[m][2], Al[m][3], wv.x, wv.y);
        }
    }
    __syncthreads();   // all Z reads complete before overwrite

    // epilogue1: bias + edge_attr tail + silu -> bf16 hi/lo back into Zh/Zl
    #pragma unroll
    for (int m = 0; m < 4; ++m) {
        #pragma unroll
        for (int t = 0; t < 4; ++t) {
            int n0 = (w * 4 + t) * 8 + qk * 2;
            int elo = m * 16 + r, ehi = elo + 8;
            float bn0 = b1_all[l * 256 + n0], bn1 = b1_all[l * 256 + n0 + 1];
            float wt0 = d_W1tail[l * 256 + n0], wt1 = d_W1tail[l * 256 + n0 + 1];
            float el = ea_s[elo], eh = ea_s[ehi];
            float v00 = c[m][t][0] + bn0 + el * wt0;
            float v01 = c[m][t][1] + bn1 + el * wt1;
            float v10 = c[m][t][2] + bn0 + eh * wt0;
            float v11 = c[m][t][3] + bn1 + eh * wt1;
            v00 *= sigmoidf_(v00); v01 *= sigmoidf_(v01);
            v10 *= sigmoidf_(v10); v11 *= sigmoidf_(v11);
            int wlo = elo * 132 + (w * 4 + t) * 4 + qk;
            int whi = ehi * 132 + (w * 4 + t) * 4 + qk;
            unsigned h0 = pk2(v00, v01);
            unsigned h1 = pk2(v10, v11);
            float a0 = __uint_as_float(h0 << 16), a1 = __uint_as_float(h0 & 0xFFFF0000u);
            float a2 = __uint_as_float(h1 << 16), a3 = __uint_as_float(h1 & 0xFFFF0000u);
            Zh[wlo] = h0; Zl[wlo] = pk2(v00 - a0, v01 - a1);
            Zh[whi] = h1; Zl[whi] = pk2(v10 - a2, v11 - a3);
        }
    }
    __syncthreads();

    // ---- GEMM2 ----
    float c2[4][2][4];
    #pragma unroll
    for (int m = 0; m < 4; ++m)
        #pragma unroll
        for (int t = 0; t < 2; ++t)
            #pragma unroll
            for (int k = 0; k < 4; ++k) c2[m][t][k] = 0.f;

    for (int s = 0; s < 16; ++s) {
        unsigned Ah[4][4], Al[4][4];
        #pragma unroll
        for (int m = 0; m < 4; ++m) {
            unsigned toff = aoff + (m * 16 * 132 + s * 8) * 4;
            ldsm4(Ah[m], zh_base + toff);
            ldsm4(Al[m], zl_base + toff);
        }
        #pragma unroll
        for (int t = 0; t < 2; ++t) {
            uint4 wv = d_W2f[((l * 16 + s) * 16 + (w * 2 + t)) * 32 + lane];
            #pragma unroll
            for (int m = 0; m < 4; ++m)
                mma_bf16(c2[m][t], Ah[m][0], Ah[m][1], Ah[m][2], Ah[m][3], wv.x, wv.y);
            #pragma unroll
            for (int m = 0; m < 4; ++m)
                mma_bf16(c2[m][t], Ah[m][0], Ah[m][1], Ah[m][2], Ah[m][3], wv.z, wv.w);
            #pragma unroll
            for (int m = 0; m < 4; ++m)
                mma_bf16(c2[m][t], Al[m][0], Al[m][1], Al[m][2], Al[m][3], wv.x, wv.y);
        }
    }

    // epilogue2: bias + scatter-add
    #pragma unroll
    for (int m = 0; m < 4; ++m) {
        #pragma unroll
        for (int t = 0; t < 2; ++t) {
            int i0 = (w * 2 + t) * 8 + qk * 2;
            int elo = m * 16 + r, ehi = elo + 8;
            float bi0 = b2_all[l * 128 + i0], bi1 = b2_all[l * 128 + i0 + 1];
            int dlo = dst_s[elo], dhi = dst_s[ehi];
            atomicAdd(&d_aggr[dlo * HID + i0],     c2[m][t][0] + bi0);
            atomicAdd(&d_aggr[dlo * HID + i0 + 1], c2[m][t][1] + bi1);
            atomicAdd(&d_aggr[dhi * HID + i0],     c2[m][t][2] + bi0);
            atomicAdd(&d_aggr[dhi * HID + i0 + 1], c2[m][t][3] + bi1);
        }
    }
}

// ---------------- gated node update + residual + LN (NB=8, float4 weights) --
// One LDG.128 feeds 32 FMA; SMEM 12 KB keeps occupancy ~50%. Re-zeros d_aggr.
__global__ void __launch_bounds__(HID) node_kernel(
    const float* __restrict__ gb_all,
    const float* __restrict__ lng_all,
    const float* __restrict__ lnb_all,
    int l) {
    __shared__ float hn[NB][HID], an[NB][HID], red[NB][HID];
    int n0 = blockIdx.x * NB;
    int j = threadIdx.x;
    #pragma unroll
    for (int n = 0; n < NB; ++n) {
        hn[n][j] = d_h[(n0 + n) * HID + j];
        an[n][j] = d_aggr[(n0 + n) * HID + j];
        d_aggr[(n0 + n) * HID + j] = 0.f;
    }
    __syncthreads();

    const float4* Wg4 = d_Wg4 + l * 64 * HID;
    float g[NB];
    float gb0 = gb_all[l * HID + j];
    #pragma unroll
    for (int n = 0; n < NB; ++n) g[n] = gb0;
    // k in [0,128): hn
    for (int kq = 0; kq < 32; ++kq) {
        float4 wv = Wg4[kq * HID + j];
        const int k0 = kq * 4;
        #pragma unroll
        for (int n = 0; n < NB; ++n) {
            g[n] = fmaf(hn[n][k0 + 0], wv.x, g[n]);
            g[n] = fmaf(hn[n][k0 + 1], wv.y, g[n]);
            g[n] = fmaf(hn[n][k0 + 2], wv.z, g[n]);
            g[n] = fmaf(hn[n][k0 + 3], wv.w, g[n]);
        }
    }
    // k in [128,256): an
    for (int kq = 32; kq < 64; ++kq) {
        float4 wv = Wg4[kq * HID + j];
        const int k0 = (kq - 32) * 4;
        #pragma unroll
        for (int n = 0; n < NB; ++n) {
            g[n] = fmaf(an[n][k0 + 0], wv.x, g[n]);
            g[n] = fmaf(an[n][k0 + 1], wv.y, g[n]);
            g[n] = fmaf(an[n][k0 + 2], wv.z, g[n]);
            g[n] = fmaf(an[n][k0 + 3], wv.w, g[n]);
        }
    }

    float t[NB];
    #pragma unroll
    for (int n = 0; n < NB; ++n) {
        float gs = sigmoidf_(g[n]);
        float hnew = gs * an[n][j] + (1.f - gs) * hn[n][j];
        t[n] = hn[n][j] + hnew;
        red[n][j] = t[n];
    }
    __syncthreads();
    #pragma unroll
    for (int s = 64; s > 0; s >>= 1) {
        if (j < s)
            #pragma unroll
            for (int n = 0; n < NB; ++n) red[n][j] += red[n][j + s];
        __syncthreads();
    }
    float mean[NB];
    #pragma unroll
    for (int n = 0; n < NB; ++n) mean[n] = red[n][0] * (1.f / HID);
    __syncthreads();
    float dd[NB];
    #pragma unroll
    for (int n = 0; n < NB; ++n) { dd[n] = t[n] - mean[n]; red[n][j] = dd[n] * dd[n]; }
    __syncthreads();
    #pragma unroll
    for (int s = 64; s > 0; s >>= 1) {
        if (j < s)
            #pragma unroll
            for (int n = 0; n < NB; ++n) red[n][j] += red[n][j + s];
        __syncthreads();
    }
    float lg = lng_all[l * HID + j], lb = lnb_all[l * HID + j];
    #pragma unroll
    for (int n = 0; n < NB; ++n) {
        float var = red[n][0] * (1.f / HID);
        d_h[(n0 + n) * HID + j] = dd[n] * rsqrtf(var + 1e-5f) * lg + lb;
    }
}

// ---------------- pooling ----------------
__global__ void pool_kernel(const int* __restrict__ batch) {
    int n = blockIdx.x;
    int j = threadIdx.x;
    int g = batch[n];
    atomicAdd(&d_sums[g * HID + j], d_h[n * HID + j]);
    if (j == 0) atomicAdd(&d_counts[g], 1.f);
}

// ---------------- x_global + projector ----------------
__global__ void final_kernel(const float* __restrict__ W1, const float* __restrict__ b1,
                             const float* __restrict__ g1, const float* __restrict__ bb1,
                             const float* __restrict__ W2, const float* __restrict__ b2,
                             const float* __restrict__ g2, const float* __restrict__ bb2,
                             float* __restrict__ out) {
    __shared__ float xg[HID], p[HID], red[HID];
    int gr = blockIdx.x;
    int j = threadIdx.x;

    float c = d_counts[gr];
    float scale = 1.f / fmaxf(c, 1.f) + 1.f / (c + 1e-6f);
    float v = d_sums[gr * HID + j] * scale;
    xg[j] = v;
    out[N_GRAPHS * LAT + gr * HID + j] = v;
    __syncthreads();

    float a = b1[j];
    #pragma unroll 4
    for (int k = 0; k < HID; ++k) a = fmaf(xg[k], W1[j * HID + k], a);
    float m = block_sum128(a, red, j) * (1.f / HID);
    float d = a - m;
    float var = block_sum128(d * d, red, j) * (1.f / HID);
    a = d * rsqrtf(var + 1e-5f) * g1[j] + bb1[j];
    a = a * sigmoidf_(a);
    p[j] = a;
    __syncthreads();

    float z = 0.f;
    if (j < LAT) {
        z = b2[j];
        #pragma unroll 4
        for (int k = 0; k < HID; ++k) z = fmaf(p[k], W2[j * HID + k], z);
    }
    float m2 = block_sum128((j < LAT) ? z : 0.f, red, j) * (1.f / LAT);
    float d2 = z - m2;
    float var2 = block_sum128((j < LAT) ? d2 * d2 : 0.f, red, j) * (1.f / LAT);
    if (j < LAT)
        out[gr * LAT + j] = d2 * rsqrtf(var2 + 1e-5f) * g2[j] + bb2[j];
}

// ---------------- launch ----------------
extern "C" void kernel_launch(void* const* d_in, const int* in_sizes, int n_in,
                              void* d_out, int out_size) {
    const float* x     = (const float*)d_in[0];
    const float* ea    = (const float*)d_in[1];
    const int*   ei    = (const int*)  d_in[2];
    const int*   batch = (const int*)  d_in[3];
    const float* embW  = (const float*)d_in[4];
    const float* embb  = (const float*)d_in[5];
    const float* embg  = (const float*)d_in[6];
    const float* emblb = (const float*)d_in[7];
    const float* m1W   = (const float*)d_in[8];
    const float* m1b   = (const float*)d_in[9];
    const float* m2W   = (const float*)d_in[10];
    const float* m2b   = (const float*)d_in[11];
    const float* gW    = (const float*)d_in[12];
    const float* gb    = (const float*)d_in[13];
    const float* lng   = (const float*)d_in[14];
    const float* lnb   = (const float*)d_in[15];
    const float* p1W   = (const float*)d_in[16];
    const float* p1b   = (const float*)d_in[17];
    const float* pl1g  = (const float*)d_in[18];
    const float* pl1b  = (const float*)d_in[19];
    const float* p2W   = (const float*)d_in[20];
    const float* p2b   = (const float*)d_in[21];
    const float* pl2g  = (const float*)d_in[22];
    const float* pl2b  = (const float*)d_in[23];
    float* out = (float*)d_out;

    const int smem_bytes = 2 * 64 * 132 * 4 + 3 * 64 * 4;   // 68352
    cudaFuncSetAttribute(edge_kernel, cudaFuncAttributeMaxDynamicSharedMemorySize, smem_bytes);

    pack_kernel<<<384, 256>>>(m1W, m2W, gW);
    embed_kernel<<<N_NODES, HID>>>(x, embW, embb, embg, emblb);

    for (int l = 0; l < NLAY; ++l) {
        edge_kernel<<<N_EDGES / ET, 256, smem_bytes>>>(ea, ei, m1b, m2b, l);
        node_kernel<<<N_NODES / NB, HID>>>(gb, lng, lnb, l);
    }

    zero_pool_kernel<<<33, 256>>>();
    pool_kernel<<<N_NODES, HID>>>(batch);
    final_kernel<<<N_GRAPHS, HID>>>(p1W, p1b, pl1g, pl1b, p2W, p2b, pl2g, pl2b, out);
}

// round 17
// speedup vs baseline: 1.3838x; 1.1599x over previous
#include <cuda_runtime.h>
#include <cuda_bf16.h>
#include <math.h>

#define N_NODES 10000
#define N_EDGES 160000
#define N_GRAPHS 64
#define HID 128
#define LAT 64
#define NLAY 3
#define ET 64          // edges per block in the edge kernel
#define NB 8           // nodes per block in node_kernel
#define NT 32          // nodes per block in pre_kernel

// ---------------- device scratch (no allocations allowed) ----------------
__device__ float d_h[N_NODES * HID];
__device__ float d_aggr[N_NODES * HID];   // zero at load; node_kernel re-zeros after reading
__device__ __align__(16) float d_P[N_NODES * 512];   // [n][0:256]=A=h@W1a^T+b1, [256:512]=B=h@W1b^T
// B-fragment packed weights (uint4 {hi01, hi89, lo01, lo89} per lane)
__device__ uint4 d_WCf[NLAY * 8 * 64 * 32];    // pre GEMM: K=128 (8 steps), N=512 (64 ntiles)
__device__ uint4 d_W2f[NLAY * 16 * 16 * 32];   // GEMM2: K=256 (16 steps), N=128 (16 ntiles)
__device__ float4 d_Wt4[NLAY * 64];            // k=256 tail column of W1, float4-packed
__device__ float d_Wgt[NLAY * 256 * HID];      // gate_W transposed (scalar, R7 form)
__device__ float d_sums[N_GRAPHS * HID];
__device__ float d_counts[N_GRAPHS];

__device__ __forceinline__ float sigmoidf_(float v) {
    return 1.f / (1.f + __expf(-v));
}
__device__ __forceinline__ unsigned pk2(float lo, float hi) {
    unsigned r;
    asm("cvt.rn.bf16x2.f32 %0, %1, %2;" : "=r"(r) : "f"(hi), "f"(lo));
    return r;
}
__device__ __forceinline__ void mma_bf16(float c[4],
                                         unsigned a0, unsigned a1, unsigned a2, unsigned a3,
                                         unsigned b0, unsigned b1) {
    asm("mma.sync.aligned.m16n8k16.row.col.f32.bf16.bf16.f32 "
        "{%0,%1,%2,%3}, {%4,%5,%6,%7}, {%8,%9}, {%0,%1,%2,%3};"
        : "+f"(c[0]), "+f"(c[1]), "+f"(c[2]), "+f"(c[3])
        : "r"(a0), "r"(a1), "r"(a2), "r"(a3), "r"(b0), "r"(b1));
}
__device__ __forceinline__ void ldsm4(unsigned r[4], unsigned addr) {
    asm volatile("ldmatrix.sync.aligned.m8n8.x4.shared.b16 {%0,%1,%2,%3}, [%4];"
        : "=r"(r[0]), "=r"(r[1]), "=r"(r[2]), "=r"(r[3]) : "r"(addr));
}
__device__ __forceinline__ void split_pack(float x, float y, unsigned& hi, unsigned& lo) {
    unsigned h = pk2(x, y);
    float a0 = __uint_as_float(h << 16), a1 = __uint_as_float(h & 0xFFFF0000u);
    hi = h;
    lo = pk2(x - a0, y - a1);
}

__device__ __forceinline__ float block_sum128(float v, float* red, int j) {
    red[j] = v;
    __syncthreads();
    #pragma unroll
    for (int s = 64; s > 0; s >>= 1) {
        if (j < s) red[j] += red[j + s];
        __syncthreads();
    }
    float r = red[0];
    __syncthreads();
    return r;
}

// ---------------- weight fragment packing (run once per launch) ----------------
__global__ void pack_kernel(const float* __restrict__ W1,   // [3][256][257]
                            const float* __restrict__ W2,   // [3][128][256]
                            const float* __restrict__ Wg) { // [3][128][256]
    int idx = blockIdx.x * blockDim.x + threadIdx.x;
    int stride = gridDim.x * blockDim.x;
    // WCf: pre-GEMM fragments over concat weight [512 out][128 in]
    //   out n<256:  W1[n][k]        (dst half)
    //   out n>=256: W1[n-256][128+k] (src half)
    const int n0 = NLAY * 8 * 64 * 32;
    for (int t = idx; t < n0; t += stride) {
        int l = t / (8 * 64 * 32);
        int r = t % (8 * 64 * 32);
        int s = r / (64 * 32);
        int r2 = r % (64 * 32);
        int nt = r2 / 32;
        int lane = r2 % 32;
        int n = nt * 8 + lane / 4;
        int k0 = s * 16 + (lane % 4) * 2;
        const float* row = (n < 256) ? (W1 + (l * 256 + n) * 257 + k0)
                                     : (W1 + (l * 256 + (n - 256)) * 257 + 128 + k0);
        float f0 = row[0], f1 = row[1], f2 = row[8], f3 = row[9];
        unsigned h01, l01, h89, l89;
        split_pack(f0, f1, h01, l01);
        split_pack(f2, f3, h89, l89);
        uint4 o; o.x = h01; o.y = h89; o.z = l01; o.w = l89;
        d_WCf[t] = o;
    }
    const int n2 = NLAY * 16 * 16 * 32;
    for (int t = idx; t < n2; t += stride) {
        int l = t / (16 * 16 * 32);
        int r = t % (16 * 16 * 32);
        int s = r / (16 * 32);
        int r2 = r % (16 * 32);
        int tt = r2 / 32;
        int lane = r2 % 32;
        int n = tt * 8 + lane / 4;
        int k0 = s * 16 + (lane % 4) * 2;
        const float* row = W2 + (l * 128 + n) * 256;
        float f0 = row[k0], f1 = row[k0 + 1], f2 = row[k0 + 8], f3 = row[k0 + 9];
        unsigned h01, l01, h89, l89;
        split_pack(f0, f1, h01, l01);
        split_pack(f2, f3, h89, l89);
        uint4 o; o.x = h01; o.y = h89; o.z = l01; o.w = l89;
        d_W2f[t] = o;
    }
    for (int t = idx; t < NLAY * 64; t += stride) {
        int l = t / 64;
        int cq = t % 64;
        float4 v;
        v.x = W1[(l * 256 + cq * 4 + 0) * 257 + 256];
        v.y = W1[(l * 256 + cq * 4 + 1) * 257 + 256];
        v.z = W1[(l * 256 + cq * 4 + 2) * 257 + 256];
        v.w = W1[(l * 256 + cq * 4 + 3) * 257 + 256];
        d_Wt4[t] = v;
    }
    const int n3 = NLAY * 128 * 256;
    for (int t = idx; t < n3; t += stride) {
        int l = t / (128 * 256);
        int r = t % (128 * 256);
        int i = r / 256;
        int k = r % 256;
        d_Wgt[l * 256 * 128 + k * 128 + i] = Wg[t];
    }
}

// ---------------- node embedding ----------------
__global__ void embed_kernel(const float* __restrict__ x,
                             const float* __restrict__ W,
                             const float* __restrict__ b,
                             const float* __restrict__ lng,
                             const float* __restrict__ lnb) {
    __shared__ float red[HID];
    int n = blockIdx.x;
    int j = threadIdx.x;
    float x0 = x[n * 3 + 0], x1 = x[n * 3 + 1], x2 = x[n * 3 + 2];
    float v = b[j] + x0 * W[j * 3 + 0] + x1 * W[j * 3 + 1] + x2 * W[j * 3 + 2];
    float m = block_sum128(v, red, j) * (1.f / HID);
    float d = v - m;
    float var = block_sum128(d * d, red, j) * (1.f / HID);
    float y = d * rsqrtf(var + 1e-5f) * lng[j] + lnb[j];
    d_h[n * HID + j] = y * sigmoidf_(y);
}

__global__ void zero_pool_kernel() {
    int idx = blockIdx.x * blockDim.x + threadIdx.x;
    if (idx < N_GRAPHS * HID) d_sums[idx] = 0.f;
    if (idx < N_GRAPHS) d_counts[idx] = 0.f;
}

// ---------------- per-node precompute: P = [h@W1a^T+b1 | h@W1b^T] ------------
// 32 nodes/block, 256 threads. K=128 (8 ksteps), N=512 (8 warps x 64 cols).
__global__ void __launch_bounds__(256, 2) pre_kernel(
    const float* __restrict__ b1_all, int l) {
    __shared__ __align__(16) unsigned Zh[NT * 68], Zl[NT * 68];
    const int tid = threadIdx.x;
    const int lane = tid & 31, w = tid >> 5;
    const int n0 = blockIdx.x * NT;

    // load h rows -> bf16 hi/lo
    {
        int row = tid >> 3, chunk = tid & 7;
        int node = n0 + row; if (node >= N_NODES) node = N_NODES - 1;
        const float4* hp = (const float4*)(d_h + node * HID) + chunk * 4;
        unsigned* oh = Zh + row * 68 + chunk * 8;
        unsigned* ol = Zl + row * 68 + chunk * 8;
        #pragma unroll
        for (int i = 0; i < 4; ++i) {
            float4 v = hp[i];
            split_pack(v.x, v.y, oh[i * 2],     ol[i * 2]);
            split_pack(v.z, v.w, oh[i * 2 + 1], ol[i * 2 + 1]);
        }
    }
    __syncthreads();

    const int r = lane >> 2, qk = lane & 3;
    const unsigned zh_base = (unsigned)__cvta_generic_to_shared(Zh);
    const unsigned zl_base = (unsigned)__cvta_generic_to_shared(Zl);
    const unsigned aoff = ((lane & 15) * 68 + ((lane >> 4) << 2)) * 4;

    float c[2][8][4];
    #pragma unroll
    for (int m = 0; m < 2; ++m)
        #pragma unroll
        for (int t = 0; t < 8; ++t)
            #pragma unroll
            for (int k = 0; k < 4; ++k) c[m][t][k] = 0.f;

    for (int s = 0; s < 8; ++s) {
        unsigned Ah[2][4], Al[2][4];
        #pragma unroll
        for (int m = 0; m < 2; ++m) {
            unsigned toff = aoff + (m * 16 * 68 + s * 8) * 4;
            ldsm4(Ah[m], zh_base + toff);
            ldsm4(Al[m], zl_base + toff);
        }
        #pragma unroll
        for (int t = 0; t < 8; ++t) {
            uint4 wv = d_WCf[((l * 8 + s) * 64 + (w * 8 + t)) * 32 + lane];
            #pragma unroll
            for (int m = 0; m < 2; ++m)
                mma_bf16(c[m][t], Ah[m][0], Ah[m][1], Ah[m][2], Ah[m][3], wv.x, wv.y);
            #pragma unroll
            for (int m = 0; m < 2; ++m)
                mma_bf16(c[m][t], Ah[m][0], Ah[m][1], Ah[m][2], Ah[m][3], wv.z, wv.w);
            #pragma unroll
            for (int m = 0; m < 2; ++m)
                mma_bf16(c[m][t], Al[m][0], Al[m][1], Al[m][2], Al[m][3], wv.x, wv.y);
        }
    }

    #pragma unroll
    for (int m = 0; m < 2; ++m) {
        #pragma unroll
        for (int t = 0; t < 8; ++t) {
            int ncol = (w * 8 + t) * 8 + qk * 2;
            float b0 = (ncol < 256) ? b1_all[l * 256 + ncol]     : 0.f;
            float b1 = (ncol < 256) ? b1_all[l * 256 + ncol + 1] : 0.f;
            int nlo = n0 + m * 16 + r, nhi = nlo + 8;
            if (nlo < N_NODES) {
                d_P[nlo * 512 + ncol]     = c[m][t][0] + b0;
                d_P[nlo * 512 + ncol + 1] = c[m][t][1] + b1;
            }
            if (nhi < N_NODES) {
                d_P[nhi * 512 + ncol]     = c[m][t][2] + b0;
                d_P[nhi * 512 + ncol + 1] = c[m][t][3] + b1;
            }
        }
    }
}

// ---------------- edge kernel: silu(A[dst]+B[src]+ea*wt) then GEMM2 ----------
__global__ void __launch_bounds__(256, 3) edge_kernel(
    const float* __restrict__ edge_attr,
    const int* __restrict__ edge_index,
    const float* __restrict__ b2_all,   // [3][128]
    int l) {
    extern __shared__ __align__(16) unsigned sm[];
    unsigned* Zh = sm;                      // 64*132 words (m1 hi)
    unsigned* Zl = sm + 64 * 132;
    int* dst_s = (int*)(sm + 2 * 64 * 132);
    int* src_s = dst_s + 64;
    float* ea_s = (float*)(src_s + 64);

    const int tid = threadIdx.x;
    const int lane = tid & 31, w = tid >> 5;
    const int e0 = blockIdx.x * ET;

    if (tid < 64) { dst_s[tid] = edge_index[N_EDGES + e0 + tid]; ea_s[tid] = edge_attr[e0 + tid]; }
    else if (tid < 128) src_s[tid - 64] = edge_index[e0 + tid - 64];
    __syncthreads();

    // gather-combine + silu + bf16 hi/lo split (m1 directly)
    {
        int e = tid >> 2, q = tid & 3;
        int de = dst_s[e], se = src_s[e];
        const float4* Ap = (const float4*)(d_P + de * 512) + q * 16;
        const float4* Bp = (const float4*)(d_P + se * 512 + 256) + q * 16;
        const float4* Wt = d_Wt4 + l * 64 + q * 16;
        float eav = ea_s[e];
        unsigned* oh = Zh + e * 132 + q * 32;
        unsigned* ol = Zl + e * 132 + q * 32;
        #pragma unroll 4
        for (int i = 0; i < 16; ++i) {
            float4 a = Ap[i], b = Bp[i], wt = Wt[i];
            float v0 = a.x + b.x + eav * wt.x;
            float v1 = a.y + b.y + eav * wt.y;
            float v2 = a.z + b.z + eav * wt.z;
            float v3 = a.w + b.w + eav * wt.w;
            v0 *= sigmoidf_(v0); v1 *= sigmoidf_(v1);
            v2 *= sigmoidf_(v2); v3 *= sigmoidf_(v3);
            split_pack(v0, v1, oh[i * 2],     ol[i * 2]);
            split_pack(v2, v3, oh[i * 2 + 1], ol[i * 2 + 1]);
        }
    }
    __syncthreads();

    const int r = lane >> 2, qk = lane & 3;
    const unsigned zh_base = (unsigned)__cvta_generic_to_shared(Zh);
    const unsigned zl_base = (unsigned)__cvta_generic_to_shared(Zl);
    const unsigned aoff = ((lane & 15) * 132 + ((lane >> 4) << 2)) * 4;

    // ---- GEMM2 ----
    float c2[4][2][4];
    #pragma unroll
    for (int m = 0; m < 4; ++m)
        #pragma unroll
        for (int t = 0; t < 2; ++t)
            #pragma unroll
            for (int k = 0; k < 4; ++k) c2[m][t][k] = 0.f;

    for (int s = 0; s < 16; ++s) {
        unsigned Ah[4][4], Al[4][4];
        #pragma unroll
        for (int m = 0; m < 4; ++m) {
            unsigned toff = aoff + (m * 16 * 132 + s * 8) * 4;
            ldsm4(Ah[m], zh_base + toff);
            ldsm4(Al[m], zl_base + toff);
        }
        #pragma unroll
        for (int t = 0; t < 2; ++t) {
            uint4 wv = d_W2f[((l * 16 + s) * 16 + (w * 2 + t)) * 32 + lane];
            #pragma unroll
            for (int m = 0; m < 4; ++m)
                mma_bf16(c2[m][t], Ah[m][0], Ah[m][1], Ah[m][2], Ah[m][3], wv.x, wv.y);
            #pragma unroll
            for (int m = 0; m < 4; ++m)
                mma_bf16(c2[m][t], Ah[m][0], Ah[m][1], Ah[m][2], Ah[m][3], wv.z, wv.w);
            #pragma unroll
            for (int m = 0; m < 4; ++m)
                mma_bf16(c2[m][t], Al[m][0], Al[m][1], Al[m][2], Al[m][3], wv.x, wv.y);
        }
    }

    // epilogue2: bias + scatter-add
    #pragma unroll
    for (int m = 0; m < 4; ++m) {
        #pragma unroll
        for (int t = 0; t < 2; ++t) {
            int i0 = (w * 2 + t) * 8 + qk * 2;
            int elo = m * 16 + r, ehi = elo + 8;
            float bi0 = b2_all[l * 128 + i0], bi1 = b2_all[l * 128 + i0 + 1];
            int dlo = dst_s[elo], dhi = dst_s[ehi];
            atomicAdd(&d_aggr[dlo * HID + i0],     c2[m][t][0] + bi0);
            atomicAdd(&d_aggr[dlo * HID + i0 + 1], c2[m][t][1] + bi1);
            atomicAdd(&d_aggr[dhi * HID + i0],     c2[m][t][2] + bi0);
            atomicAdd(&d_aggr[dhi * HID + i0 + 1], c2[m][t][3] + bi1);
        }
    }
}

// ---------------- gated node update + residual + LN (NB=8, scalar weights) --
// R7 form; re-zeros d_aggr for the next layer/replay.
__global__ void __launch_bounds__(HID) node_kernel(
    const float* __restrict__ gb_all,
    const float* __restrict__ lng_all,
    const float* __restrict__ lnb_all,
    int l) {
    __shared__ float hn[NB][HID], an[NB][HID], red[NB][HID];
    int n0 = blockIdx.x * NB;
    int j = threadIdx.x;
    #pragma unroll
    for (int n = 0; n < NB; ++n) {
        hn[n][j] = d_h[(n0 + n) * HID + j];
        an[n][j] = d_aggr[(n0 + n) * HID + j];
        d_aggr[(n0 + n) * HID + j] = 0.f;
    }
    __syncthreads();

    const float* Wg = d_Wgt + l * 256 * HID;
    float g[NB];
    float gb0 = gb_all[l * HID + j];
    #pragma unroll
    for (int n = 0; n < NB; ++n) g[n] = gb0;
    for (int k = 0; k < HID; ++k) {
        float wv = Wg[k * HID + j];
        #pragma unroll
        for (int n = 0; n < NB; ++n) g[n] = fmaf(hn[n][k], wv, g[n]);
    }
    for (int k = 0; k < HID; ++k) {
        float wv = Wg[(HID + k) * HID + j];
        #pragma unroll
        for (int n = 0; n < NB; ++n) g[n] = fmaf(an[n][k], wv, g[n]);
    }

    float t[NB];
    #pragma unroll
    for (int n = 0; n < NB; ++n) {
        float gs = sigmoidf_(g[n]);
        float hnew = gs * an[n][j] + (1.f - gs) * hn[n][j];
        t[n] = hn[n][j] + hnew;
        red[n][j] = t[n];
    }
    __syncthreads();
    #pragma unroll
    for (int s = 64; s > 0; s >>= 1) {
        if (j < s)
            #pragma unroll
            for (int n = 0; n < NB; ++n) red[n][j] += red[n][j + s];
        __syncthreads();
    }
    float mean[NB];
    #pragma unroll
    for (int n = 0; n < NB; ++n) mean[n] = red[n][0] * (1.f / HID);
    __syncthreads();
    float dd[NB];
    #pragma unroll
    for (int n = 0; n < NB; ++n) { dd[n] = t[n] - mean[n]; red[n][j] = dd[n] * dd[n]; }
    __syncthreads();
    #pragma unroll
    for (int s = 64; s > 0; s >>= 1) {
        if (j < s)
            #pragma unroll
            for (int n = 0; n < NB; ++n) red[n][j] += red[n][j + s];
        __syncthreads();
    }
    float lg = lng_all[l * HID + j], lb = lnb_all[l * HID + j];
    #pragma unroll
    for (int n = 0; n < NB; ++n) {
        float var = red[n][0] * (1.f / HID);
        d_h[(n0 + n) * HID + j] = dd[n] * rsqrtf(var + 1e-5f) * lg + lb;
    }
}

// ---------------- pooling ----------------
__global__ void pool_kernel(const int* __restrict__ batch) {
    int n = blockIdx.x;
    int j = threadIdx.x;
    int g = batch[n];
    atomicAdd(&d_sums[g * HID + j], d_h[n * HID + j]);
    if (j == 0) atomicAdd(&d_counts[g], 1.f);
}

// ---------------- x_global + projector ----------------
__global__ void final_kernel(const float* __restrict__ W1, const float* __restrict__ b1,
                             const float* __restrict__ g1, const float* __restrict__ bb1,
                             const float* __restrict__ W2, const float* __restrict__ b2,
                             const float* __restrict__ g2, const float* __restrict__ bb2,
                             float* __restrict__ out) {
    __shared__ float xg[HID], p[HID], red[HID];
    int gr = blockIdx.x;
    int j = threadIdx.x;

    float c = d_counts[gr];
    float scale = 1.f / fmaxf(c, 1.f) + 1.f / (c + 1e-6f);
    float v = d_sums[gr * HID + j] * scale;
    xg[j] = v;
    out[N_GRAPHS * LAT + gr * HID + j] = v;
    __syncthreads();

    float a = b1[j];
    #pragma unroll 4
    for (int k = 0; k < HID; ++k) a = fmaf(xg[k], W1[j * HID + k], a);
    float m = block_sum128(a, red, j) * (1.f / HID);
    float d = a - m;
    float var = block_sum128(d * d, red, j) * (1.f / HID);
    a = d * rsqrtf(var + 1e-5f) * g1[j] + bb1[j];
    a = a * sigmoidf_(a);
    p[j] = a;
    __syncthreads();

    float z = 0.f;
    if (j < LAT) {
        z = b2[j];
        #pragma unroll 4
        for (int k = 0; k < HID; ++k) z = fmaf(p[k], W2[j * HID + k], z);
    }
    float m2 = block_sum128((j < LAT) ? z : 0.f, red, j) * (1.f / LAT);
    float d2 = z - m2;
    float var2 = block_sum128((j < LAT) ? d2 * d2 : 0.f, red, j) * (1.f / LAT);
    if (j < LAT)
        out[gr * LAT + j] = d2 * rsqrtf(var2 + 1e-5f) * g2[j] + bb2[j];
}

// ---------------- launch ----------------
extern "C" void kernel_launch(void* const* d_in, const int* in_sizes, int n_in,
                              void* d_out, int out_size) {
    const float* x     = (const float*)d_in[0];
    const float* ea    = (const float*)d_in[1];
    const int*   ei    = (const int*)  d_in[2];
    const int*   batch = (const int*)  d_in[3];
    const float* embW  = (const float*)d_in[4];
    const float* embb  = (const float*)d_in[5];
    const float* embg  = (const float*)d_in[6];
    const float* emblb = (const float*)d_in[7];
    const float* m1W   = (const float*)d_in[8];
    const float* m1b   = (const float*)d_in[9];
    const float* m2W   = (const float*)d_in[10];
    const float* m2b   = (const float*)d_in[11];
    const float* gW    = (const float*)d_in[12];
    const float* gb    = (const float*)d_in[13];
    const float* lng   = (const float*)d_in[14];
    const float* lnb   = (const float*)d_in[15];
    const float* p1W   = (const float*)d_in[16];
    const float* p1b   = (const float*)d_in[17];
    const float* pl1g  = (const float*)d_in[18];
    const float* pl1b  = (const float*)d_in[19];
    const float* p2W   = (const float*)d_in[20];
    const float* p2b   = (const float*)d_in[21];
    const float* pl2g  = (const float*)d_in[22];
    const float* pl2b  = (const float*)d_in[23];
    float* out = (float*)d_out;

    const int smem_bytes = 2 * 64 * 132 * 4 + 3 * 64 * 4;   // 68352
    cudaFuncSetAttribute(edge_kernel, cudaFuncAttributeMaxDynamicSharedMemorySize, smem_bytes);

    pack_kernel<<<384, 256>>>(m1W, m2W, gW);
    embed_kernel<<<N_NODES, HID>>>(x, embW, embb, embg, emblb);

    const int pre_grid = (N_NODES + NT - 1) / NT;   // 313
    for (int l = 0; l < NLAY; ++l) {
        pre_kernel<<<pre_grid, 256>>>(m1b, l);
        edge_kernel<<<N_EDGES / ET, 256, smem_bytes>>>(ea, ei, m2b, l);
        node_kernel<<<N_NODES / NB, HID>>>(gb, lng, lnb, l);
    }

    zero_pool_kernel<<<33, 256>>>();
    pool_kernel<<<N_NODES, HID>>>(batch);
    final_kernel<<<N_GRAPHS, HID>>>(p1W, p1b, pl1g, pl1b, p2W, p2b, pl2g, pl2b, out);
}